// round 8
// baseline (speedup 1.0000x reference)
#include <cuda_runtime.h>
#include <cuda_bf16.h>
#include <math.h>
#include <stdint.h>

// Problem constants
#define Bc   4
#define Lc   4096
#define Dc   1024
#define Hc   16
#define Dhc  64
#define Mtot (Bc*Lc)        // 16384 rows
#define NC   32             // scan chunks per sequence
#define CHUNK (Lc/NC)       // 128

// GEMM tiling (mma.sync path): 128x128 tile, 2 CTAs/SM
#define MT 128
#define NT 128
#define KT 32               // k per stage
#define NKC (Dc/KT)         // 32 k-chunks
#define A_TILE (MT*KT*2)            // 8192
#define W_TILE (NT*KT*2)            // 8192
#define OFF_AH 0
#define OFF_AL (A_TILE)
#define OFF_WH (2*A_TILE)
#define OFF_WL (3*A_TILE)
#define STAGE_BYTES (4*A_TILE)      // 32768
#define NSTAGE 3
#define GEMM_SMEM (NSTAGE*STAGE_BYTES)     // 98304

// Conflict-free swizzle: 16B-chunk c (0..3) xored with (row>>1)&3.
#define SWZ(row, ch) ((uint32_t)(row) * 64 + (uint32_t)((((ch) ^ (((row) >> 1) & 3)) & 3) * 16))

// ---------------------------------------------------------------------------
// Scratch (__device__ globals per allocation-free rule)
// ---------------------------------------------------------------------------
__device__ float g_q[Mtot*Dc];                 // q
__device__ float g_v[Mtot*Dc];                 // v
__device__ float g_g[Mtot*Dc];                 // gate pre-activation
__device__ float g_chunkS[Bc*Hc*NC*Dhc];
__device__ float g_carry [Bc*Hc*NC*Dhc];
__device__ __nv_bfloat16 g_xh[Mtot*Dc];
__device__ __nv_bfloat16 g_xl[Mtot*Dc];
__device__ __nv_bfloat16 g_zh[Mtot*Dc];
__device__ __nv_bfloat16 g_zl[Mtot*Dc];
__device__ __nv_bfloat16 g_wh[4*Dc*Dc];        // Wq,Wv,Wg,Wo hi
__device__ __nv_bfloat16 g_wl[4*Dc*Dc];        // lo

// ---------------------------------------------------------------------------
// PTX helpers (base ISA only: cp.async, ldmatrix, mma.sync)
// ---------------------------------------------------------------------------
__device__ __forceinline__ uint32_t smem_to_u32(const void* p) {
    uint32_t a;
    asm("{ .reg .u64 t; cvta.to.shared.u64 t, %1; cvt.u32.u64 %0, t; }" : "=r"(a) : "l"(p));
    return a;
}

#define CP16(dst, src) \
    asm volatile("cp.async.cg.shared.global [%0], [%1], 16;" :: "r"(dst), "l"(src) : "memory")

__device__ __forceinline__ void ldsm_x4(uint32_t (&r)[4], uint32_t addr) {
    asm volatile("ldmatrix.sync.aligned.m8n8.x4.shared.b16 {%0,%1,%2,%3}, [%4];"
        : "=r"(r[0]), "=r"(r[1]), "=r"(r[2]), "=r"(r[3]) : "r"(addr));
}

__device__ __forceinline__ void mma16816(float (&c)[4], const uint32_t (&a)[4],
                                         uint32_t b0, uint32_t b1) {
    asm volatile("mma.sync.aligned.m16n8k16.row.col.f32.bf16.bf16.f32 "
        "{%0,%1,%2,%3}, {%4,%5,%6,%7}, {%8,%9}, {%0,%1,%2,%3};"
        : "+f"(c[0]), "+f"(c[1]), "+f"(c[2]), "+f"(c[3])
        : "r"(a[0]), "r"(a[1]), "r"(a[2]), "r"(a[3]), "r"(b0), "r"(b1));
}

// ---------------------------------------------------------------------------
// Split fp32 -> (hi bf16, lo bf16); batched over up to 5 tensors via blockIdx.y
// ---------------------------------------------------------------------------
struct SplitArgs {
    const float* src[5];
    __nv_bfloat16* hi[5];
    __nv_bfloat16* lo[5];
    int n4[5];
};

__global__ __launch_bounds__(256)
void split_kernel(const SplitArgs args)
{
    const int z = blockIdx.y;
    const float* s = args.src[z];
    __nv_bfloat16* hi = args.hi[z];
    __nv_bfloat16* lo = args.lo[z];
    const int n4 = args.n4[z];

    int i = blockIdx.x * 256 + threadIdx.x;
    if (i >= n4) return;
    float4 f = ((const float4*)s)[i];
    __nv_bfloat16 h0 = __float2bfloat16(f.x);
    __nv_bfloat16 h1 = __float2bfloat16(f.y);
    __nv_bfloat16 h2 = __float2bfloat16(f.z);
    __nv_bfloat16 h3 = __float2bfloat16(f.w);
    __nv_bfloat16 l0 = __float2bfloat16(f.x - __bfloat162float(h0));
    __nv_bfloat16 l1 = __float2bfloat16(f.y - __bfloat162float(h1));
    __nv_bfloat16 l2 = __float2bfloat16(f.z - __bfloat162float(h2));
    __nv_bfloat16 l3 = __float2bfloat16(f.w - __bfloat162float(h3));
    __nv_bfloat162 hp0(h0, h1), hp1(h2, h3), lp0(l0, l1), lp1(l2, l3);
    uint2 hv, lv;
    hv.x = *(uint32_t*)&hp0; hv.y = *(uint32_t*)&hp1;
    lv.x = *(uint32_t*)&lp0; lv.y = *(uint32_t*)&lp1;
    ((uint2*)hi)[i] = hv;
    ((uint2*)lo)[i] = lv;
}

// ---------------------------------------------------------------------------
// mma.sync GEMM: identical to R7 config (128x128 tile, 2 CTAs/SM)
// ---------------------------------------------------------------------------
struct GemmArgs {
    const __nv_bfloat16* Ah;
    const __nv_bfloat16* Al;
    const __nv_bfloat16* Wh[3];
    const __nv_bfloat16* Wl[3];
    float* C[3];
};

__global__ __launch_bounds__(256, 2)
void gemm_mma(const GemmArgs args)
{
    extern __shared__ char smem[];
    const uint32_t sbase = smem_to_u32(smem);
    const int tid  = threadIdx.x;
    const int lane = tid & 31;
    const int wid  = tid >> 5;
    const int wm   = wid & 3;
    const int wn   = wid >> 2;
    const int bn   = blockIdx.x * NT;
    const int bm   = blockIdx.y * MT;
    const int z    = blockIdx.z;

    const __nv_bfloat16* __restrict__ Ah = args.Ah;
    const __nv_bfloat16* __restrict__ Al = args.Al;
    const __nv_bfloat16* __restrict__ Wh = args.Wh[z];
    const __nv_bfloat16* __restrict__ Wl = args.Wl[z];
    float* __restrict__ C = args.C[z];

    const int row0 = tid >> 2;
    const int ch0  = tid & 3;

    auto load_stage = [&](int st, int kc) {
        const uint32_t sb = sbase + (uint32_t)st * STAGE_BYTES;
        const int k0 = kc * KT;
        #pragma unroll
        for (int rep = 0; rep < 2; rep++) {
            int row = row0 + rep * 64;
            uint32_t sw = SWZ(row, ch0);
            const __nv_bfloat16* pa = Ah + (size_t)(bm + row) * Dc + k0 + ch0 * 8;
            const __nv_bfloat16* pl = Al + (size_t)(bm + row) * Dc + k0 + ch0 * 8;
            const __nv_bfloat16* pw = Wh + (size_t)(bn + row) * Dc + k0 + ch0 * 8;
            const __nv_bfloat16* pq = Wl + (size_t)(bn + row) * Dc + k0 + ch0 * 8;
            CP16(sb + OFF_AH + sw, pa);
            CP16(sb + OFF_AL + sw, pl);
            CP16(sb + OFF_WH + sw, pw);
            CP16(sb + OFF_WL + sw, pq);
        }
        asm volatile("cp.async.commit_group;" ::: "memory");
    };

    float c[2][8][4];
    #pragma unroll
    for (int i = 0; i < 2; i++)
        #pragma unroll
        for (int j = 0; j < 8; j++)
            #pragma unroll
            for (int k = 0; k < 4; k++) c[i][j][k] = 0.0f;

    load_stage(0, 0);
    load_stage(1, 1);

    const int a_r  = lane & 15;
    const int a_kc = lane >> 4;
    const int b_r  = ((lane >> 4) << 3) + (lane & 7);
    const int b_kc = (lane >> 3) & 1;

    for (int kc = 0; kc < NKC; kc++) {
        const int st = kc % NSTAGE;
        asm volatile("cp.async.wait_group 1;" ::: "memory");
        __syncthreads();

        if (kc + 2 < NKC) load_stage((kc + 2) % NSTAGE, kc + 2);
        else asm volatile("cp.async.commit_group;" ::: "memory");

        const uint32_t sb = sbase + (uint32_t)st * STAGE_BYTES;

        #pragma unroll
        for (int ks = 0; ks < 2; ks++) {
            uint32_t ah[2][4], al[2][4];
            #pragma unroll
            for (int mi = 0; mi < 2; mi++) {
                int row = wm * 32 + mi * 16 + a_r;
                int kk  = ks * 2 + a_kc;
                uint32_t sw = SWZ(row, kk);
                ldsm_x4(ah[mi], sb + OFF_AH + sw);
                ldsm_x4(al[mi], sb + OFF_AL + sw);
            }
            #pragma unroll
            for (int half = 0; half < 2; half++) {
                uint32_t bh[2][4], bl[2][4];
                #pragma unroll
                for (int p = 0; p < 2; p++) {
                    int pr  = half * 2 + p;
                    int row = wn * 64 + pr * 16 + b_r;
                    int kk  = ks * 2 + b_kc;
                    uint32_t sw = SWZ(row, kk);
                    ldsm_x4(bh[p], sb + OFF_WH + sw);
                    ldsm_x4(bl[p], sb + OFF_WL + sw);
                }
                #pragma unroll
                for (int mi = 0; mi < 2; mi++)
                    #pragma unroll
                    for (int p = 0; p < 2; p++) {
                        int ni = (half * 2 + p) * 2;
                        mma16816(c[mi][ni+0], ah[mi], bh[p][0], bh[p][1]);
                        mma16816(c[mi][ni+1], ah[mi], bh[p][2], bh[p][3]);
                    }
                #pragma unroll
                for (int mi = 0; mi < 2; mi++)
                    #pragma unroll
                    for (int p = 0; p < 2; p++) {
                        int ni = (half * 2 + p) * 2;
                        mma16816(c[mi][ni+0], ah[mi], bl[p][0], bl[p][1]);
                        mma16816(c[mi][ni+1], ah[mi], bl[p][2], bl[p][3]);
                    }
                #pragma unroll
                for (int mi = 0; mi < 2; mi++)
                    #pragma unroll
                    for (int p = 0; p < 2; p++) {
                        int ni = (half * 2 + p) * 2;
                        mma16816(c[mi][ni+0], al[mi], bh[p][0], bh[p][1]);
                        mma16816(c[mi][ni+1], al[mi], bh[p][2], bh[p][3]);
                    }
            }
        }
    }

    const int er = lane >> 2;
    const int ec = (lane & 3) * 2;
    #pragma unroll
    for (int mi = 0; mi < 2; mi++) {
        #pragma unroll
        for (int ni = 0; ni < 8; ni++) {
            size_t r0g = (size_t)(bm + wm * 32 + mi * 16 + er);
            size_t cg  = (size_t)(bn + wn * 64 + ni * 8 + ec);
            float2* p0 = (float2*)(C + r0g * Dc + cg);
            float2* p1 = (float2*)(C + (r0g + 8) * Dc + cg);
            *p0 = make_float2(c[mi][ni][0], c[mi][ni][1]);
            *p1 = make_float2(c[mi][ni][2], c[mi][ni][3]);
        }
    }
}

// ---------------------------------------------------------------------------
// Retention scan
// ---------------------------------------------------------------------------
__device__ __forceinline__ float lam_of(const float* beta, int h)
{
    float lam = 1.0f - exp2f(-beta[h]);
    lam = fmaxf(lam, 1.17549435e-38f);
    lam = fminf(lam, 1.0f);
    return lam;
}

__global__ __launch_bounds__(64)
void scan_pass1(const float* __restrict__ v, const float* __restrict__ beta)
{
    int blk = blockIdx.x;
    int cc  = blk % NC;
    int bh  = blk / NC;
    int h   = bh % Hc;
    int b   = bh / Hc;
    int dh  = threadIdx.x;

    float lam = lam_of(beta, h);
    size_t off = ((size_t)(b*Lc + cc*CHUNK)) * Dc + h*Dhc + dh;

    float s = 0.0f;
    #pragma unroll 4
    for (int t = 0; t < CHUNK; t++) {
        s = fmaf(lam, s, v[off]);
        off += Dc;
    }
    g_chunkS[(size_t)(bh*NC + cc)*Dhc + dh] = s;
}

// Pass 2: batched loads (MLP ~32), then register scan.
__global__ __launch_bounds__(256)
void scan_pass2(const float* __restrict__ beta)
{
    int idx = blockIdx.x * blockDim.x + threadIdx.x;  // 0..4095
    int dh  = idx & 63;
    int bh  = idx >> 6;
    int h   = bh & (Hc - 1);

    float lam = lam_of(beta, h);
    float lamP = lam;
    #pragma unroll
    for (int i = 0; i < 7; i++) lamP = lamP * lamP;   // lam^128

    float cs[NC];
    #pragma unroll
    for (int cc = 0; cc < NC; cc++)
        cs[cc] = g_chunkS[(size_t)(bh*NC + cc)*Dhc + dh];

    float carry = 0.0f;
    #pragma unroll
    for (int cc = 0; cc < NC; cc++) {
        g_carry[(size_t)(bh*NC + cc)*Dhc + dh] = carry;
        carry = fmaf(lamP, carry, cs[cc]);
    }
}

// ---------------------------------------------------------------------------
// Fused: local scan (with carry) + ret=q*s + LayerNorm + SiLU gate + bf16 split.
// Block = (chunk, batch), 1024 threads = one full feature row per timestep.
// ---------------------------------------------------------------------------
__global__ __launch_bounds__(1024)
void fused_scan_ln(const float* __restrict__ v, const float* __restrict__ q,
                   const float* __restrict__ g, const float* __restrict__ beta,
                   const float* __restrict__ gamma, const float* __restrict__ lbeta,
                   __nv_bfloat16* __restrict__ zh, __nv_bfloat16* __restrict__ zl)
{
    const int cc  = blockIdx.x;    // chunk
    const int b   = blockIdx.y;    // batch
    const int tid = threadIdx.x;   // feature index c = h*64+dh
    const int h   = tid >> 6;
    const int dh  = tid & 63;

    const float lam = lam_of(beta, h);
    float s = g_carry[(size_t)((b*Hc + h)*NC + cc)*Dhc + dh];
    const float gam = gamma[tid];
    const float bet = lbeta[tid];

    __shared__ float wsum[32], wsq[32], bcast[2];

    size_t off = ((size_t)(b*Lc + cc*CHUNK)) * Dc + tid;
    float vv = v[off], qq = q[off], gg = g[off];

    for (int t = 0; t < CHUNK; t++) {
        // prefetch next row while we reduce this one
        size_t noff = off + Dc;
        float vn = 0.0f, qn = 0.0f, gn = 0.0f;
        if (t + 1 < CHUNK) { vn = v[noff]; qn = q[noff]; gn = g[noff]; }

        s = fmaf(lam, s, vv);
        float r = qq * s;

        // block-wide sum / sumsq over 1024 threads
        float su = r, sq = r * r;
        #pragma unroll
        for (int o = 16; o > 0; o >>= 1) {
            su += __shfl_xor_sync(0xffffffffu, su, o);
            sq += __shfl_xor_sync(0xffffffffu, sq, o);
        }
        if ((tid & 31) == 0) { wsum[tid >> 5] = su; wsq[tid >> 5] = sq; }
        __syncthreads();
        if (tid < 32) {
            float a = wsum[tid], c2 = wsq[tid];
            #pragma unroll
            for (int o = 16; o > 0; o >>= 1) {
                a  += __shfl_xor_sync(0xffffffffu, a,  o);
                c2 += __shfl_xor_sync(0xffffffffu, c2, o);
            }
            if (tid == 0) {
                float mu  = a * (1.0f / (float)Dc);
                float var = c2 * (1.0f / (float)Dc) - mu * mu;
                bcast[0] = mu;
                bcast[1] = rsqrtf(var + 1e-5f);
            }
        }
        __syncthreads();
        float mu = bcast[0], rstd = bcast[1];

        float y = (r - mu) * rstd * gam + bet;
        float zz = y * (gg / (1.0f + expf(-gg)));

        __nv_bfloat16 hb = __float2bfloat16(zz);
        __nv_bfloat16 lb = __float2bfloat16(zz - __bfloat162float(hb));
        zh[off] = hb;
        zl[off] = lb;

        off = noff; vv = vn; qq = qn; gg = gn;
    }
}

// ---------------------------------------------------------------------------
// Launch
// ---------------------------------------------------------------------------
extern "C" void kernel_launch(void* const* d_in, const int* in_sizes, int n_in,
                              void* d_out, int out_size)
{
    const float* x      = (const float*)d_in[0];
    const float* Wq     = (const float*)d_in[1];
    const float* Wv     = (const float*)d_in[2];
    const float* Wo     = (const float*)d_in[3];
    const float* Wg     = (const float*)d_in[4];
    const float* beta   = (const float*)d_in[5];
    const float* gamma  = (const float*)d_in[6];
    const float* lbeta  = (const float*)d_in[7];
    float* out          = (float*)d_out;

    float *q, *v, *g;
    __nv_bfloat16 *xh, *xl, *zh, *zl, *wh, *wl;
    cudaGetSymbolAddress((void**)&q, g_q);
    cudaGetSymbolAddress((void**)&v, g_v);
    cudaGetSymbolAddress((void**)&g, g_g);
    cudaGetSymbolAddress((void**)&xh, g_xh);
    cudaGetSymbolAddress((void**)&xl, g_xl);
    cudaGetSymbolAddress((void**)&zh, g_zh);
    cudaGetSymbolAddress((void**)&zl, g_zl);
    cudaGetSymbolAddress((void**)&wh, g_wh);
    cudaGetSymbolAddress((void**)&wl, g_wl);

    cudaFuncSetAttribute(gemm_mma, cudaFuncAttributeMaxDynamicSharedMemorySize, GEMM_SMEM);

    // Splits: one fused launch (x + 4 weights), grid.y selects tensor
    SplitArgs sa;
    sa.src[0] = x;  sa.hi[0] = xh; sa.lo[0] = xl; sa.n4[0] = Mtot*Dc/4;
    sa.src[1] = Wq; sa.hi[1] = wh + 0*(size_t)Dc*Dc; sa.lo[1] = wl + 0*(size_t)Dc*Dc; sa.n4[1] = Dc*Dc/4;
    sa.src[2] = Wv; sa.hi[2] = wh + 1*(size_t)Dc*Dc; sa.lo[2] = wl + 1*(size_t)Dc*Dc; sa.n4[2] = Dc*Dc/4;
    sa.src[3] = Wg; sa.hi[3] = wh + 2*(size_t)Dc*Dc; sa.lo[3] = wl + 2*(size_t)Dc*Dc; sa.n4[3] = Dc*Dc/4;
    sa.src[4] = Wo; sa.hi[4] = wh + 3*(size_t)Dc*Dc; sa.lo[4] = wl + 3*(size_t)Dc*Dc; sa.n4[4] = Dc*Dc/4;
    dim3 sgrid((Mtot*Dc/4 + 255)/256, 5);
    split_kernel<<<sgrid, 256>>>(sa);

    // Fused q/v/g projection GEMMs (z-indexed)
    GemmArgs a1;
    a1.Ah = xh; a1.Al = xl;
    a1.Wh[0] = wh + 0*(size_t)Dc*Dc; a1.Wl[0] = wl + 0*(size_t)Dc*Dc; a1.C[0] = q;
    a1.Wh[1] = wh + 1*(size_t)Dc*Dc; a1.Wl[1] = wl + 1*(size_t)Dc*Dc; a1.C[1] = v;
    a1.Wh[2] = wh + 2*(size_t)Dc*Dc; a1.Wl[2] = wl + 2*(size_t)Dc*Dc; a1.C[2] = g;
    dim3 grid_qvg(Dc/NT, Mtot/MT, 3);   // (8, 128, 3)
    gemm_mma<<<grid_qvg, 256, GEMM_SMEM>>>(a1);

    scan_pass1<<<Bc*Hc*NC, 64>>>(v, beta);
    scan_pass2<<<(Bc*Hc*Dhc)/256, 256>>>(beta);

    // Fused scan+LN+gate+split -> zh, zl
    dim3 fgrid(NC, Bc);   // (32, 4) blocks of 1024 threads
    fused_scan_ln<<<fgrid, 1024>>>(v, q, g, beta, gamma, lbeta, zh, zl);

    // Output GEMM
    GemmArgs a2;
    a2.Ah = zh; a2.Al = zl;
    a2.Wh[0] = wh + 3*(size_t)Dc*Dc; a2.Wl[0] = wl + 3*(size_t)Dc*Dc; a2.C[0] = out;
    a2.Wh[1] = a2.Wh[0]; a2.Wl[1] = a2.Wl[0]; a2.C[1] = out;
    a2.Wh[2] = a2.Wh[0]; a2.Wl[2] = a2.Wl[0]; a2.C[2] = out;
    dim3 grid_o(Dc/NT, Mtot/MT, 1);     // (8, 128, 1)
    gemm_mma<<<grid_o, 256, GEMM_SMEM>>>(a2);
}

// round 9
// speedup vs baseline: 1.4056x; 1.4056x over previous
#include <cuda_runtime.h>
#include <cuda_fp16.h>
#include <math.h>
#include <stdint.h>

// Problem constants
#define Bc   4
#define Lc   4096
#define Dc   1024
#define Hc   16
#define Dhc  64
#define Mtot (Bc*Lc)        // 16384 rows
#define NC   32             // scan chunks per sequence
#define CHUNK (Lc/NC)       // 128

// GEMM tiling: 128x128 tile, fp16 2-term (A hi only; W hi+lo), 2 CTAs/SM
#define MT 128
#define NT 128
#define KT 32               // k per stage
#define NKC (Dc/KT)         // 32 k-chunks
#define TILE_B (MT*KT*2)            // 8192 bytes per operand tile
#define OFF_AH 0
#define OFF_WH (TILE_B)
#define OFF_WL (2*TILE_B)
#define STAGE_BYTES (3*TILE_B)      // 24576
#define NSTAGE 3
#define GEMM_SMEM (NSTAGE*STAGE_BYTES)     // 73728

// Conflict-free swizzle: 16B-chunk c (0..3) xored with (row>>1)&3.
#define SWZ(row, ch) ((uint32_t)(row) * 64 + (uint32_t)((((ch) ^ (((row) >> 1) & 3)) & 3) * 16))

// ---------------------------------------------------------------------------
// Scratch (__device__ globals per allocation-free rule)
// ---------------------------------------------------------------------------
__device__ float g_q[Mtot*Dc];                 // q -> ret
__device__ float g_v[Mtot*Dc];                 // v
__device__ float g_g[Mtot*Dc];                 // gate pre-activation
__device__ float g_chunkS[Bc*Hc*NC*Dhc];
__device__ float g_carry [Bc*Hc*NC*Dhc];
__device__ __half g_xh[Mtot*Dc];               // x in fp16
__device__ __half g_zh[Mtot*Dc];               // z in fp16
__device__ __half g_wh[4*Dc*Dc];               // Wq,Wv,Wg,Wo hi
__device__ __half g_wl[4*Dc*Dc];               // lo

// ---------------------------------------------------------------------------
// PTX helpers
// ---------------------------------------------------------------------------
__device__ __forceinline__ uint32_t smem_to_u32(const void* p) {
    uint32_t a;
    asm("{ .reg .u64 t; cvta.to.shared.u64 t, %1; cvt.u32.u64 %0, t; }" : "=r"(a) : "l"(p));
    return a;
}

#define CP16(dst, src) \
    asm volatile("cp.async.cg.shared.global [%0], [%1], 16;" :: "r"(dst), "l"(src) : "memory")

__device__ __forceinline__ void ldsm_x4(uint32_t (&r)[4], uint32_t addr) {
    asm volatile("ldmatrix.sync.aligned.m8n8.x4.shared.b16 {%0,%1,%2,%3}, [%4];"
        : "=r"(r[0]), "=r"(r[1]), "=r"(r[2]), "=r"(r[3]) : "r"(addr));
}

__device__ __forceinline__ void mma16816(float (&c)[4], const uint32_t (&a)[4],
                                         uint32_t b0, uint32_t b1) {
    asm volatile("mma.sync.aligned.m16n8k16.row.col.f32.f16.f16.f32 "
        "{%0,%1,%2,%3}, {%4,%5,%6,%7}, {%8,%9}, {%0,%1,%2,%3};"
        : "+f"(c[0]), "+f"(c[1]), "+f"(c[2]), "+f"(c[3])
        : "r"(a[0]), "r"(a[1]), "r"(a[2]), "r"(a[3]), "r"(b0), "r"(b1));
}

// ---------------------------------------------------------------------------
// Weight split fp32 -> (hi fp16, lo fp16); batched over 4 weights
// ---------------------------------------------------------------------------
struct SplitWArgs {
    const float* src[4];
    __half* hi[4];
    __half* lo[4];
};

__global__ __launch_bounds__(256)
void split_w_kernel(const SplitWArgs args)
{
    const int z = blockIdx.y;
    const float* s = args.src[z];
    __half* hi = args.hi[z];
    __half* lo = args.lo[z];

    int i = blockIdx.x * 256 + threadIdx.x;
    if (i >= Dc*Dc/4) return;
    float4 f = ((const float4*)s)[i];
    __half h0 = __float2half_rn(f.x), h1 = __float2half_rn(f.y);
    __half h2 = __float2half_rn(f.z), h3 = __float2half_rn(f.w);
    __half l0 = __float2half_rn(f.x - __half2float(h0));
    __half l1 = __float2half_rn(f.y - __half2float(h1));
    __half l2 = __float2half_rn(f.z - __half2float(h2));
    __half l3 = __float2half_rn(f.w - __half2float(h3));
    __half2 hp0(h0, h1), hp1(h2, h3), lp0(l0, l1), lp1(l2, l3);
    uint2 hv, lv;
    hv.x = *(uint32_t*)&hp0; hv.y = *(uint32_t*)&hp1;
    lv.x = *(uint32_t*)&lp0; lv.y = *(uint32_t*)&lp1;
    ((uint2*)hi)[i] = hv;
    ((uint2*)lo)[i] = lv;
}

// Activation convert fp32 -> fp16 (hi only)
__global__ __launch_bounds__(256)
void cvt_kernel(const float* __restrict__ s, __half* __restrict__ hi, int n4)
{
    int i = blockIdx.x * 256 + threadIdx.x;
    if (i >= n4) return;
    float4 f = ((const float4*)s)[i];
    __half2 hp0 = __floats2half2_rn(f.x, f.y);
    __half2 hp1 = __floats2half2_rn(f.z, f.w);
    uint2 hv;
    hv.x = *(uint32_t*)&hp0; hv.y = *(uint32_t*)&hp1;
    ((uint2*)hi)[i] = hv;
}

// ---------------------------------------------------------------------------
// mma.sync GEMM: C[m,n] = sum_k A[m,k]*W[n,k], fp16 2-term, fp32 out.
// 128x128 CTA tile, 8 warps (32x64 each), K-chunk 32, 3-stage, 2 CTAs/SM.
// ---------------------------------------------------------------------------
struct GemmArgs {
    const __half* Ah;
    const __half* Wh[3];
    const __half* Wl[3];
    float* C[3];
};

__global__ __launch_bounds__(256, 2)
void gemm_mma(const GemmArgs args)
{
    extern __shared__ char smem[];
    const uint32_t sbase = smem_to_u32(smem);
    const int tid  = threadIdx.x;
    const int lane = tid & 31;
    const int wid  = tid >> 5;
    const int wm   = wid & 3;
    const int wn   = wid >> 2;
    const int bn   = blockIdx.x * NT;
    const int bm   = blockIdx.y * MT;
    const int z    = blockIdx.z;

    const __half* __restrict__ Ah = args.Ah;
    const __half* __restrict__ Wh = args.Wh[z];
    const __half* __restrict__ Wl = args.Wl[z];
    float* __restrict__ C = args.C[z];

    const int row0 = tid >> 2;
    const int ch0  = tid & 3;

    auto load_stage = [&](int st, int kc) {
        const uint32_t sb = sbase + (uint32_t)st * STAGE_BYTES;
        const int k0 = kc * KT;
        #pragma unroll
        for (int rep = 0; rep < 2; rep++) {
            int row = row0 + rep * 64;
            uint32_t sw = SWZ(row, ch0);
            const __half* pa = Ah + (size_t)(bm + row) * Dc + k0 + ch0 * 8;
            const __half* pw = Wh + (size_t)(bn + row) * Dc + k0 + ch0 * 8;
            const __half* pq = Wl + (size_t)(bn + row) * Dc + k0 + ch0 * 8;
            CP16(sb + OFF_AH + sw, pa);
            CP16(sb + OFF_WH + sw, pw);
            CP16(sb + OFF_WL + sw, pq);
        }
        asm volatile("cp.async.commit_group;" ::: "memory");
    };

    float c[2][8][4];
    #pragma unroll
    for (int i = 0; i < 2; i++)
        #pragma unroll
        for (int j = 0; j < 8; j++)
            #pragma unroll
            for (int k = 0; k < 4; k++) c[i][j][k] = 0.0f;

    load_stage(0, 0);
    load_stage(1, 1);

    const int a_r  = lane & 15;
    const int a_kc = lane >> 4;
    const int b_r  = ((lane >> 4) << 3) + (lane & 7);
    const int b_kc = (lane >> 3) & 1;

    for (int kc = 0; kc < NKC; kc++) {
        const int st = kc % NSTAGE;
        asm volatile("cp.async.wait_group 1;" ::: "memory");
        __syncthreads();

        if (kc + 2 < NKC) load_stage((kc + 2) % NSTAGE, kc + 2);
        else asm volatile("cp.async.commit_group;" ::: "memory");

        const uint32_t sb = sbase + (uint32_t)st * STAGE_BYTES;

        #pragma unroll
        for (int ks = 0; ks < 2; ks++) {
            uint32_t ah[2][4];
            #pragma unroll
            for (int mi = 0; mi < 2; mi++) {
                int row = wm * 32 + mi * 16 + a_r;
                int kk  = ks * 2 + a_kc;
                ldsm_x4(ah[mi], sb + OFF_AH + SWZ(row, kk));
            }
            #pragma unroll
            for (int half = 0; half < 2; half++) {
                uint32_t bh[2][4], bl[2][4];
                #pragma unroll
                for (int p = 0; p < 2; p++) {
                    int pr  = half * 2 + p;
                    int row = wn * 64 + pr * 16 + b_r;
                    int kk  = ks * 2 + b_kc;
                    uint32_t sw = SWZ(row, kk);
                    ldsm_x4(bh[p], sb + OFF_WH + sw);
                    ldsm_x4(bl[p], sb + OFF_WL + sw);
                }
                // Term 1: Ah x Wh (8 distinct accumulators)
                #pragma unroll
                for (int mi = 0; mi < 2; mi++)
                    #pragma unroll
                    for (int p = 0; p < 2; p++) {
                        int ni = (half * 2 + p) * 2;
                        mma16816(c[mi][ni+0], ah[mi], bh[p][0], bh[p][1]);
                        mma16816(c[mi][ni+1], ah[mi], bh[p][2], bh[p][3]);
                    }
                // Term 2: Ah x Wl
                #pragma unroll
                for (int mi = 0; mi < 2; mi++)
                    #pragma unroll
                    for (int p = 0; p < 2; p++) {
                        int ni = (half * 2 + p) * 2;
                        mma16816(c[mi][ni+0], ah[mi], bl[p][0], bl[p][1]);
                        mma16816(c[mi][ni+1], ah[mi], bl[p][2], bl[p][3]);
                    }
            }
        }
    }

    const int er = lane >> 2;
    const int ec = (lane & 3) * 2;
    #pragma unroll
    for (int mi = 0; mi < 2; mi++) {
        #pragma unroll
        for (int ni = 0; ni < 8; ni++) {
            size_t r0g = (size_t)(bm + wm * 32 + mi * 16 + er);
            size_t cg  = (size_t)(bn + wn * 64 + ni * 8 + ec);
            float2* p0 = (float2*)(C + r0g * Dc + cg);
            float2* p1 = (float2*)(C + (r0g + 8) * Dc + cg);
            *p0 = make_float2(c[mi][ni][0], c[mi][ni][1]);
            *p1 = make_float2(c[mi][ni][2], c[mi][ni][3]);
        }
    }
}

// ---------------------------------------------------------------------------
// Retention scan
// ---------------------------------------------------------------------------
__device__ __forceinline__ float lam_of(const float* beta, int h)
{
    float lam = 1.0f - exp2f(-beta[h]);
    lam = fmaxf(lam, 1.17549435e-38f);
    lam = fminf(lam, 1.0f);
    return lam;
}

__global__ __launch_bounds__(64)
void scan_pass1(const float* __restrict__ v, const float* __restrict__ beta)
{
    int blk = blockIdx.x;
    int cc  = blk % NC;
    int bh  = blk / NC;
    int h   = bh % Hc;
    int b   = bh / Hc;
    int dh  = threadIdx.x;

    float lam = lam_of(beta, h);
    size_t off = ((size_t)(b*Lc + cc*CHUNK)) * Dc + h*Dhc + dh;

    float s = 0.0f;
    #pragma unroll 4
    for (int t = 0; t < CHUNK; t++) {
        s = fmaf(lam, s, v[off]);
        off += Dc;
    }
    g_chunkS[(size_t)(bh*NC + cc)*Dhc + dh] = s;
}

// Pass 2: batched loads (MLP ~32), then register scan.
__global__ __launch_bounds__(256)
void scan_pass2(const float* __restrict__ beta)
{
    int idx = blockIdx.x * blockDim.x + threadIdx.x;  // 0..4095
    int dh  = idx & 63;
    int bh  = idx >> 6;
    int h   = bh & (Hc - 1);

    float lam = lam_of(beta, h);
    float lamP = lam;
    #pragma unroll
    for (int i = 0; i < 7; i++) lamP = lamP * lamP;   // lam^128

    float cs[NC];
    #pragma unroll
    for (int cc = 0; cc < NC; cc++)
        cs[cc] = g_chunkS[(size_t)(bh*NC + cc)*Dhc + dh];

    float carry = 0.0f;
    #pragma unroll
    for (int cc = 0; cc < NC; cc++) {
        g_carry[(size_t)(bh*NC + cc)*Dhc + dh] = carry;
        carry = fmaf(lamP, carry, cs[cc]);
    }
}

__global__ __launch_bounds__(64)
void scan_pass3(const float* __restrict__ v, float* __restrict__ q,
                const float* __restrict__ beta)
{
    int blk = blockIdx.x;
    int cc  = blk % NC;
    int bh  = blk / NC;
    int h   = bh % Hc;
    int b   = bh / Hc;
    int dh  = threadIdx.x;

    float lam = lam_of(beta, h);
    size_t off = ((size_t)(b*Lc + cc*CHUNK)) * Dc + h*Dhc + dh;

    float s = g_carry[(size_t)(bh*NC + cc)*Dhc + dh];
    #pragma unroll 4
    for (int t = 0; t < CHUNK; t++) {
        s = fmaf(lam, s, v[off]);
        q[off] = q[off] * s;
        off += Dc;
    }
}

// ---------------------------------------------------------------------------
// Fused LayerNorm(ret) * SiLU(gate) -> z fp16
// ---------------------------------------------------------------------------
__global__ __launch_bounds__(256)
void ln_gate_kernel(const float* __restrict__ ret, const float* __restrict__ gate,
                    const float* __restrict__ gamma, const float* __restrict__ lbeta,
                    __half* __restrict__ zh)
{
    const size_t row = blockIdx.x;
    const int tid = threadIdx.x;

    const float4 r = ((const float4*)(ret  + row*Dc))[tid];
    const float4 g = ((const float4*)(gate + row*Dc))[tid];

    float s  = r.x + r.y + r.z + r.w;
    float ss = r.x*r.x + r.y*r.y + r.z*r.z + r.w*r.w;

    #pragma unroll
    for (int o = 16; o > 0; o >>= 1) {
        s  += __shfl_xor_sync(0xffffffffu, s,  o);
        ss += __shfl_xor_sync(0xffffffffu, ss, o);
    }
    __shared__ float shs[8], shq[8];
    if ((tid & 31) == 0) { shs[tid>>5] = s; shq[tid>>5] = ss; }
    __syncthreads();

    float tot = 0.0f, totq = 0.0f;
    #pragma unroll
    for (int i = 0; i < 8; i++) { tot += shs[i]; totq += shq[i]; }

    const float inv = 1.0f / (float)Dc;
    float mu   = tot * inv;
    float var  = totq * inv - mu * mu;
    float rstd = rsqrtf(var + 1e-5f);

    const float4 gm = ((const float4*)gamma)[tid];
    const float4 bt = ((const float4*)lbeta)[tid];

    float4 o;
    o.x = ((r.x - mu)*rstd*gm.x + bt.x) * (g.x / (1.0f + expf(-g.x)));
    o.y = ((r.y - mu)*rstd*gm.y + bt.y) * (g.y / (1.0f + expf(-g.y)));
    o.z = ((r.z - mu)*rstd*gm.z + bt.z) * (g.z / (1.0f + expf(-g.z)));
    o.w = ((r.w - mu)*rstd*gm.w + bt.w) * (g.w / (1.0f + expf(-g.w)));

    __half2 hp0 = __floats2half2_rn(o.x, o.y);
    __half2 hp1 = __floats2half2_rn(o.z, o.w);
    uint2 hv;
    hv.x = *(uint32_t*)&hp0; hv.y = *(uint32_t*)&hp1;
    ((uint2*)(zh + row*Dc))[tid] = hv;
}

// ---------------------------------------------------------------------------
// Launch
// ---------------------------------------------------------------------------
extern "C" void kernel_launch(void* const* d_in, const int* in_sizes, int n_in,
                              void* d_out, int out_size)
{
    const float* x      = (const float*)d_in[0];
    const float* Wq     = (const float*)d_in[1];
    const float* Wv     = (const float*)d_in[2];
    const float* Wo     = (const float*)d_in[3];
    const float* Wg     = (const float*)d_in[4];
    const float* beta   = (const float*)d_in[5];
    const float* gamma  = (const float*)d_in[6];
    const float* lbeta  = (const float*)d_in[7];
    float* out          = (float*)d_out;

    float *q, *v, *g;
    __half *xh, *zh, *wh, *wl;
    cudaGetSymbolAddress((void**)&q, g_q);
    cudaGetSymbolAddress((void**)&v, g_v);
    cudaGetSymbolAddress((void**)&g, g_g);
    cudaGetSymbolAddress((void**)&xh, g_xh);
    cudaGetSymbolAddress((void**)&zh, g_zh);
    cudaGetSymbolAddress((void**)&wh, g_wh);
    cudaGetSymbolAddress((void**)&wl, g_wl);

    cudaFuncSetAttribute(gemm_mma, cudaFuncAttributeMaxDynamicSharedMemorySize, GEMM_SMEM);

    // Weight splits (4 weights, batched)
    SplitWArgs sw;
    sw.src[0] = Wq; sw.hi[0] = wh + 0*(size_t)Dc*Dc; sw.lo[0] = wl + 0*(size_t)Dc*Dc;
    sw.src[1] = Wv; sw.hi[1] = wh + 1*(size_t)Dc*Dc; sw.lo[1] = wl + 1*(size_t)Dc*Dc;
    sw.src[2] = Wg; sw.hi[2] = wh + 2*(size_t)Dc*Dc; sw.lo[2] = wl + 2*(size_t)Dc*Dc;
    sw.src[3] = Wo; sw.hi[3] = wh + 3*(size_t)Dc*Dc; sw.lo[3] = wl + 3*(size_t)Dc*Dc;
    dim3 wgrid((Dc*Dc/4 + 255)/256, 4);
    split_w_kernel<<<wgrid, 256>>>(sw);

    // x -> fp16
    cvt_kernel<<<(Mtot*Dc/4 + 255)/256, 256>>>(x, xh, Mtot*Dc/4);

    // Fused q/v/g projection GEMMs (z-indexed)
    GemmArgs a1;
    a1.Ah = xh;
    a1.Wh[0] = wh + 0*(size_t)Dc*Dc; a1.Wl[0] = wl + 0*(size_t)Dc*Dc; a1.C[0] = q;
    a1.Wh[1] = wh + 1*(size_t)Dc*Dc; a1.Wl[1] = wl + 1*(size_t)Dc*Dc; a1.C[1] = v;
    a1.Wh[2] = wh + 2*(size_t)Dc*Dc; a1.Wl[2] = wl + 2*(size_t)Dc*Dc; a1.C[2] = g;
    dim3 grid_qvg(Dc/NT, Mtot/MT, 3);   // (8, 128, 3)
    gemm_mma<<<grid_qvg, 256, GEMM_SMEM>>>(a1);

    scan_pass1<<<Bc*Hc*NC, 64>>>(v, beta);
    scan_pass2<<<(Bc*Hc*Dhc)/256, 256>>>(beta);
    scan_pass3<<<Bc*Hc*NC, 64>>>(v, q, beta);   // q now holds ret

    ln_gate_kernel<<<Mtot, 256>>>(q, g, gamma, lbeta, zh);

    // Output GEMM
    GemmArgs a2;
    a2.Ah = zh;
    a2.Wh[0] = wh + 3*(size_t)Dc*Dc; a2.Wl[0] = wl + 3*(size_t)Dc*Dc; a2.C[0] = out;
    a2.Wh[1] = a2.Wh[0]; a2.Wl[1] = a2.Wl[0]; a2.C[1] = out;
    a2.Wh[2] = a2.Wh[0]; a2.Wl[2] = a2.Wl[0]; a2.C[2] = out;
    dim3 grid_o(Dc/NT, Mtot/MT, 1);     // (8, 128, 1)
    gemm_mma<<<grid_o, 256, GEMM_SMEM>>>(a2);
}

// round 10
// speedup vs baseline: 1.4527x; 1.0335x over previous
#include <cuda_runtime.h>
#include <cuda_fp16.h>
#include <math.h>
#include <stdint.h>

// Problem constants
#define Bc   4
#define Lc   4096
#define Dc   1024
#define Hc   16
#define Dhc  64
#define Mtot (Bc*Lc)        // 16384 rows
#define NC   32             // scan chunks per sequence
#define CHUNK (Lc/NC)       // 128

// GEMM tiling: 128x128 tile, fp16 2-term (A hi only; W hi+lo), 2 CTAs/SM
#define MT 128
#define NT 128
#define KT 32               // k per stage
#define NKC (Dc/KT)         // 32 k-chunks
#define TILE_B (MT*KT*2)            // 8192 bytes per operand tile
#define OFF_AH 0
#define OFF_WH (TILE_B)
#define OFF_WL (2*TILE_B)
#define STAGE_BYTES (3*TILE_B)      // 24576
#define NSTAGE 4
#define GEMM_SMEM (NSTAGE*STAGE_BYTES)     // 98304 -> 2 CTAs/SM

// Conflict-free swizzle: 16B-chunk c (0..3) xored with (row>>1)&3.
#define SWZ(row, ch) ((uint32_t)(row) * 64 + (uint32_t)((((ch) ^ (((row) >> 1) & 3)) & 3) * 16))

// ---------------------------------------------------------------------------
// Scratch (__device__ globals per allocation-free rule)
// ---------------------------------------------------------------------------
__device__ float g_q[Mtot*Dc];                 // q -> ret
__device__ float g_v[Mtot*Dc];                 // v
__device__ float g_g[Mtot*Dc];                 // gate pre-activation
__device__ float g_chunkS[Bc*Hc*NC*Dhc];
__device__ float g_carry [Bc*Hc*NC*Dhc];
__device__ __half g_xh[Mtot*Dc];               // x in fp16
__device__ __half g_zh[Mtot*Dc];               // z in fp16
__device__ __half g_wh[4*Dc*Dc];               // Wq,Wv,Wg,Wo hi
__device__ __half g_wl[4*Dc*Dc];               // lo

// ---------------------------------------------------------------------------
// PTX helpers
// ---------------------------------------------------------------------------
__device__ __forceinline__ uint32_t smem_to_u32(const void* p) {
    uint32_t a;
    asm("{ .reg .u64 t; cvta.to.shared.u64 t, %1; cvt.u32.u64 %0, t; }" : "=r"(a) : "l"(p));
    return a;
}

#define CP16(dst, src) \
    asm volatile("cp.async.cg.shared.global [%0], [%1], 16;" :: "r"(dst), "l"(src) : "memory")

__device__ __forceinline__ void ldsm_x4(uint32_t (&r)[4], uint32_t addr) {
    asm volatile("ldmatrix.sync.aligned.m8n8.x4.shared.b16 {%0,%1,%2,%3}, [%4];"
        : "=r"(r[0]), "=r"(r[1]), "=r"(r[2]), "=r"(r[3]) : "r"(addr));
}

__device__ __forceinline__ void mma16816(float (&c)[4], const uint32_t (&a)[4],
                                         uint32_t b0, uint32_t b1) {
    asm volatile("mma.sync.aligned.m16n8k16.row.col.f32.f16.f16.f32 "
        "{%0,%1,%2,%3}, {%4,%5,%6,%7}, {%8,%9}, {%0,%1,%2,%3};"
        : "+f"(c[0]), "+f"(c[1]), "+f"(c[2]), "+f"(c[3])
        : "r"(a[0]), "r"(a[1]), "r"(a[2]), "r"(a[3]), "r"(b0), "r"(b1));
}

// ---------------------------------------------------------------------------
// Weight split fp32 -> (hi fp16, lo fp16); batched over 4 weights
// ---------------------------------------------------------------------------
struct SplitWArgs {
    const float* src[4];
    __half* hi[4];
    __half* lo[4];
};

__global__ __launch_bounds__(256)
void split_w_kernel(const SplitWArgs args)
{
    const int z = blockIdx.y;
    const float* s = args.src[z];
    __half* hi = args.hi[z];
    __half* lo = args.lo[z];

    int i = blockIdx.x * 256 + threadIdx.x;
    if (i >= Dc*Dc/4) return;
    float4 f = ((const float4*)s)[i];
    __half h0 = __float2half_rn(f.x), h1 = __float2half_rn(f.y);
    __half h2 = __float2half_rn(f.z), h3 = __float2half_rn(f.w);
    __half l0 = __float2half_rn(f.x - __half2float(h0));
    __half l1 = __float2half_rn(f.y - __half2float(h1));
    __half l2 = __float2half_rn(f.z - __half2float(h2));
    __half l3 = __float2half_rn(f.w - __half2float(h3));
    __half2 hp0(h0, h1), hp1(h2, h3), lp0(l0, l1), lp1(l2, l3);
    uint2 hv, lv;
    hv.x = *(uint32_t*)&hp0; hv.y = *(uint32_t*)&hp1;
    lv.x = *(uint32_t*)&lp0; lv.y = *(uint32_t*)&lp1;
    ((uint2*)hi)[i] = hv;
    ((uint2*)lo)[i] = lv;
}

// Activation convert fp32 -> fp16 (hi only)
__global__ __launch_bounds__(256)
void cvt_kernel(const float* __restrict__ s, __half* __restrict__ hi, int n4)
{
    int i = blockIdx.x * 256 + threadIdx.x;
    if (i >= n4) return;
    float4 f = ((const float4*)s)[i];
    __half2 hp0 = __floats2half2_rn(f.x, f.y);
    __half2 hp1 = __floats2half2_rn(f.z, f.w);
    uint2 hv;
    hv.x = *(uint32_t*)&hp0; hv.y = *(uint32_t*)&hp1;
    ((uint2*)hi)[i] = hv;
}

// ---------------------------------------------------------------------------
// mma.sync GEMM: C[m,n] = sum_k A[m,k]*W[n,k], fp16 2-term, fp32 out.
// 128x128 CTA tile, 8 warps (32x64 each), K-chunk 32, 4-stage, 2 CTAs/SM.
// ---------------------------------------------------------------------------
struct GemmArgs {
    const __half* Ah;
    const __half* Wh[3];
    const __half* Wl[3];
    float* C[3];
};

__global__ __launch_bounds__(256, 2)
void gemm_mma(const GemmArgs args)
{
    extern __shared__ char smem[];
    const uint32_t sbase = smem_to_u32(smem);
    const int tid  = threadIdx.x;
    const int lane = tid & 31;
    const int wid  = tid >> 5;
    const int wm   = wid & 3;
    const int wn   = wid >> 2;
    const int bn   = blockIdx.x * NT;
    const int bm   = blockIdx.y * MT;
    const int z    = blockIdx.z;

    const __half* __restrict__ Ah = args.Ah;
    const __half* __restrict__ Wh = args.Wh[z];
    const __half* __restrict__ Wl = args.Wl[z];
    float* __restrict__ C = args.C[z];

    const int row0 = tid >> 2;
    const int ch0  = tid & 3;

    auto load_stage = [&](int st, int kc) {
        const uint32_t sb = sbase + (uint32_t)st * STAGE_BYTES;
        const int k0 = kc * KT;
        #pragma unroll
        for (int rep = 0; rep < 2; rep++) {
            int row = row0 + rep * 64;
            uint32_t sw = SWZ(row, ch0);
            const __half* pa = Ah + (size_t)(bm + row) * Dc + k0 + ch0 * 8;
            const __half* pw = Wh + (size_t)(bn + row) * Dc + k0 + ch0 * 8;
            const __half* pq = Wl + (size_t)(bn + row) * Dc + k0 + ch0 * 8;
            CP16(sb + OFF_AH + sw, pa);
            CP16(sb + OFF_WH + sw, pw);
            CP16(sb + OFF_WL + sw, pq);
        }
        asm volatile("cp.async.commit_group;" ::: "memory");
    };

    float c[2][8][4];
    #pragma unroll
    for (int i = 0; i < 2; i++)
        #pragma unroll
        for (int j = 0; j < 8; j++)
            #pragma unroll
            for (int k = 0; k < 4; k++) c[i][j][k] = 0.0f;

    load_stage(0, 0);
    load_stage(1, 1);
    load_stage(2, 2);

    const int a_r  = lane & 15;
    const int a_kc = lane >> 4;
    const int b_r  = ((lane >> 4) << 3) + (lane & 7);
    const int b_kc = (lane >> 3) & 1;

    for (int kc = 0; kc < NKC; kc++) {
        const int st = kc % NSTAGE;
        asm volatile("cp.async.wait_group 2;" ::: "memory");
        __syncthreads();

        if (kc + 3 < NKC) load_stage((kc + 3) % NSTAGE, kc + 3);
        else asm volatile("cp.async.commit_group;" ::: "memory");

        const uint32_t sb = sbase + (uint32_t)st * STAGE_BYTES;

        #pragma unroll
        for (int ks = 0; ks < 2; ks++) {
            uint32_t ah[2][4];
            #pragma unroll
            for (int mi = 0; mi < 2; mi++) {
                int row = wm * 32 + mi * 16 + a_r;
                int kk  = ks * 2 + a_kc;
                ldsm_x4(ah[mi], sb + OFF_AH + SWZ(row, kk));
            }
            #pragma unroll
            for (int half = 0; half < 2; half++) {
                uint32_t bh[2][4], bl[2][4];
                #pragma unroll
                for (int p = 0; p < 2; p++) {
                    int pr  = half * 2 + p;
                    int row = wn * 64 + pr * 16 + b_r;
                    int kk  = ks * 2 + b_kc;
                    uint32_t sw = SWZ(row, kk);
                    ldsm_x4(bh[p], sb + OFF_WH + sw);
                    ldsm_x4(bl[p], sb + OFF_WL + sw);
                }
                // Term 1: Ah x Wh (8 distinct accumulators)
                #pragma unroll
                for (int mi = 0; mi < 2; mi++)
                    #pragma unroll
                    for (int p = 0; p < 2; p++) {
                        int ni = (half * 2 + p) * 2;
                        mma16816(c[mi][ni+0], ah[mi], bh[p][0], bh[p][1]);
                        mma16816(c[mi][ni+1], ah[mi], bh[p][2], bh[p][3]);
                    }
                // Term 2: Ah x Wl
                #pragma unroll
                for (int mi = 0; mi < 2; mi++)
                    #pragma unroll
                    for (int p = 0; p < 2; p++) {
                        int ni = (half * 2 + p) * 2;
                        mma16816(c[mi][ni+0], ah[mi], bl[p][0], bl[p][1]);
                        mma16816(c[mi][ni+1], ah[mi], bl[p][2], bl[p][3]);
                    }
            }
        }
    }

    const int er = lane >> 2;
    const int ec = (lane & 3) * 2;
    #pragma unroll
    for (int mi = 0; mi < 2; mi++) {
        #pragma unroll
        for (int ni = 0; ni < 8; ni++) {
            size_t r0g = (size_t)(bm + wm * 32 + mi * 16 + er);
            size_t cg  = (size_t)(bn + wn * 64 + ni * 8 + ec);
            float2* p0 = (float2*)(C + r0g * Dc + cg);
            float2* p1 = (float2*)(C + (r0g + 8) * Dc + cg);
            *p0 = make_float2(c[mi][ni][0], c[mi][ni][1]);
            *p1 = make_float2(c[mi][ni][2], c[mi][ni][3]);
        }
    }
}

// ---------------------------------------------------------------------------
// Retention scan
// ---------------------------------------------------------------------------
__device__ __forceinline__ float lam_of(const float* beta, int h)
{
    float lam = 1.0f - exp2f(-beta[h]);
    lam = fmaxf(lam, 1.17549435e-38f);
    lam = fminf(lam, 1.0f);
    return lam;
}

// Pass 1: deep unroll -> 16 outstanding loads per thread (latency-bound fix)
__global__ __launch_bounds__(64)
void scan_pass1(const float* __restrict__ v, const float* __restrict__ beta)
{
    int blk = blockIdx.x;
    int cc  = blk % NC;
    int bh  = blk / NC;
    int h   = bh % Hc;
    int b   = bh / Hc;
    int dh  = threadIdx.x;

    float lam = lam_of(beta, h);
    size_t off = ((size_t)(b*Lc + cc*CHUNK)) * Dc + h*Dhc + dh;

    float s = 0.0f;
    #pragma unroll
    for (int t0 = 0; t0 < CHUNK; t0 += 16) {
        float vals[16];
        #pragma unroll
        for (int j = 0; j < 16; j++)
            vals[j] = v[off + (size_t)j * Dc];
        #pragma unroll
        for (int j = 0; j < 16; j++)
            s = fmaf(lam, s, vals[j]);
        off += (size_t)16 * Dc;
    }
    g_chunkS[(size_t)(bh*NC + cc)*Dhc + dh] = s;
}

// Pass 2: batched loads (MLP ~32), then register scan.
__global__ __launch_bounds__(256)
void scan_pass2(const float* __restrict__ beta)
{
    int idx = blockIdx.x * blockDim.x + threadIdx.x;  // 0..4095
    int dh  = idx & 63;
    int bh  = idx >> 6;
    int h   = bh & (Hc - 1);

    float lam = lam_of(beta, h);
    float lamP = lam;
    #pragma unroll
    for (int i = 0; i < 7; i++) lamP = lamP * lamP;   // lam^128

    float cs[NC];
    #pragma unroll
    for (int cc = 0; cc < NC; cc++)
        cs[cc] = g_chunkS[(size_t)(bh*NC + cc)*Dhc + dh];

    float carry = 0.0f;
    #pragma unroll
    for (int cc = 0; cc < NC; cc++) {
        g_carry[(size_t)(bh*NC + cc)*Dhc + dh] = carry;
        carry = fmaf(lamP, carry, cs[cc]);
    }
}

// Pass 3: 8-deep batched loads of v and q, then scan + product.
__global__ __launch_bounds__(64)
void scan_pass3(const float* __restrict__ v, float* __restrict__ q,
                const float* __restrict__ beta)
{
    int blk = blockIdx.x;
    int cc  = blk % NC;
    int bh  = blk / NC;
    int h   = bh % Hc;
    int b   = bh / Hc;
    int dh  = threadIdx.x;

    float lam = lam_of(beta, h);
    size_t off = ((size_t)(b*Lc + cc*CHUNK)) * Dc + h*Dhc + dh;

    float s = g_carry[(size_t)(bh*NC + cc)*Dhc + dh];
    #pragma unroll
    for (int t0 = 0; t0 < CHUNK; t0 += 8) {
        float vv[8], qq[8];
        #pragma unroll
        for (int j = 0; j < 8; j++) {
            vv[j] = v[off + (size_t)j * Dc];
            qq[j] = q[off + (size_t)j * Dc];
        }
        #pragma unroll
        for (int j = 0; j < 8; j++) {
            s = fmaf(lam, s, vv[j]);
            q[off + (size_t)j * Dc] = qq[j] * s;
        }
        off += (size_t)8 * Dc;
    }
}

// ---------------------------------------------------------------------------
// Fused LayerNorm(ret) * SiLU(gate) -> z fp16
// ---------------------------------------------------------------------------
__global__ __launch_bounds__(256)
void ln_gate_kernel(const float* __restrict__ ret, const float* __restrict__ gate,
                    const float* __restrict__ gamma, const float* __restrict__ lbeta,
                    __half* __restrict__ zh)
{
    const size_t row = blockIdx.x;
    const int tid = threadIdx.x;

    const float4 r = ((const float4*)(ret  + row*Dc))[tid];
    const float4 g = ((const float4*)(gate + row*Dc))[tid];

    float s  = r.x + r.y + r.z + r.w;
    float ss = r.x*r.x + r.y*r.y + r.z*r.z + r.w*r.w;

    #pragma unroll
    for (int o = 16; o > 0; o >>= 1) {
        s  += __shfl_xor_sync(0xffffffffu, s,  o);
        ss += __shfl_xor_sync(0xffffffffu, ss, o);
    }
    __shared__ float shs[8], shq[8];
    if ((tid & 31) == 0) { shs[tid>>5] = s; shq[tid>>5] = ss; }
    __syncthreads();

    float tot = 0.0f, totq = 0.0f;
    #pragma unroll
    for (int i = 0; i < 8; i++) { tot += shs[i]; totq += shq[i]; }

    const float inv = 1.0f / (float)Dc;
    float mu   = tot * inv;
    float var  = totq * inv - mu * mu;
    float rstd = rsqrtf(var + 1e-5f);

    const float4 gm = ((const float4*)gamma)[tid];
    const float4 bt = ((const float4*)lbeta)[tid];

    float4 o;
    o.x = ((r.x - mu)*rstd*gm.x + bt.x) * (g.x / (1.0f + expf(-g.x)));
    o.y = ((r.y - mu)*rstd*gm.y + bt.y) * (g.y / (1.0f + expf(-g.y)));
    o.z = ((r.z - mu)*rstd*gm.z + bt.z) * (g.z / (1.0f + expf(-g.z)));
    o.w = ((r.w - mu)*rstd*gm.w + bt.w) * (g.w / (1.0f + expf(-g.w)));

    __half2 hp0 = __floats2half2_rn(o.x, o.y);
    __half2 hp1 = __floats2half2_rn(o.z, o.w);
    uint2 hv;
    hv.x = *(uint32_t*)&hp0; hv.y = *(uint32_t*)&hp1;
    ((uint2*)(zh + row*Dc))[tid] = hv;
}

// ---------------------------------------------------------------------------
// Launch
// ---------------------------------------------------------------------------
extern "C" void kernel_launch(void* const* d_in, const int* in_sizes, int n_in,
                              void* d_out, int out_size)
{
    const float* x      = (const float*)d_in[0];
    const float* Wq     = (const float*)d_in[1];
    const float* Wv     = (const float*)d_in[2];
    const float* Wo     = (const float*)d_in[3];
    const float* Wg     = (const float*)d_in[4];
    const float* beta   = (const float*)d_in[5];
    const float* gamma  = (const float*)d_in[6];
    const float* lbeta  = (const float*)d_in[7];
    float* out          = (float*)d_out;

    float *q, *v, *g;
    __half *xh, *zh, *wh, *wl;
    cudaGetSymbolAddress((void**)&q, g_q);
    cudaGetSymbolAddress((void**)&v, g_v);
    cudaGetSymbolAddress((void**)&g, g_g);
    cudaGetSymbolAddress((void**)&xh, g_xh);
    cudaGetSymbolAddress((void**)&zh, g_zh);
    cudaGetSymbolAddress((void**)&wh, g_wh);
    cudaGetSymbolAddress((void**)&wl, g_wl);

    cudaFuncSetAttribute(gemm_mma, cudaFuncAttributeMaxDynamicSharedMemorySize, GEMM_SMEM);

    // Weight splits (4 weights, batched)
    SplitWArgs sw;
    sw.src[0] = Wq; sw.hi[0] = wh + 0*(size_t)Dc*Dc; sw.lo[0] = wl + 0*(size_t)Dc*Dc;
    sw.src[1] = Wv; sw.hi[1] = wh + 1*(size_t)Dc*Dc; sw.lo[1] = wl + 1*(size_t)Dc*Dc;
    sw.src[2] = Wg; sw.hi[2] = wh + 2*(size_t)Dc*Dc; sw.lo[2] = wl + 2*(size_t)Dc*Dc;
    sw.src[3] = Wo; sw.hi[3] = wh + 3*(size_t)Dc*Dc; sw.lo[3] = wl + 3*(size_t)Dc*Dc;
    dim3 wgrid((Dc*Dc/4 + 255)/256, 4);
    split_w_kernel<<<wgrid, 256>>>(sw);

    // x -> fp16
    cvt_kernel<<<(Mtot*Dc/4 + 255)/256, 256>>>(x, xh, Mtot*Dc/4);

    // Fused q/v/g projection GEMMs (z-indexed)
    GemmArgs a1;
    a1.Ah = xh;
    a1.Wh[0] = wh + 0*(size_t)Dc*Dc; a1.Wl[0] = wl + 0*(size_t)Dc*Dc; a1.C[0] = q;
    a1.Wh[1] = wh + 1*(size_t)Dc*Dc; a1.Wl[1] = wl + 1*(size_t)Dc*Dc; a1.C[1] = v;
    a1.Wh[2] = wh + 2*(size_t)Dc*Dc; a1.Wl[2] = wl + 2*(size_t)Dc*Dc; a1.C[2] = g;
    dim3 grid_qvg(Dc/NT, Mtot/MT, 3);   // (8, 128, 3)
    gemm_mma<<<grid_qvg, 256, GEMM_SMEM>>>(a1);

    scan_pass1<<<Bc*Hc*NC, 64>>>(v, beta);
    scan_pass2<<<(Bc*Hc*Dhc)/256, 256>>>(beta);
    scan_pass3<<<Bc*Hc*NC, 64>>>(v, q, beta);   // q now holds ret

    ln_gate_kernel<<<Mtot, 256>>>(q, g, gamma, lbeta, zh);

    // Output GEMM
    GemmArgs a2;
    a2.Ah = zh;
    a2.Wh[0] = wh + 3*(size_t)Dc*Dc; a2.Wl[0] = wl + 3*(size_t)Dc*Dc; a2.C[0] = out;
    a2.Wh[1] = a2.Wh[0]; a2.Wl[1] = a2.Wl[0]; a2.C[1] = out;
    a2.Wh[2] = a2.Wh[0]; a2.Wl[2] = a2.Wl[0]; a2.C[2] = out;
    dim3 grid_o(Dc/NT, Mtot/MT, 1);     // (8, 128, 1)
    gemm_mma<<<grid_o, 256, GEMM_SMEM>>>(a2);
}

// round 11
// speedup vs baseline: 1.4734x; 1.0143x over previous
#include <cuda_runtime.h>
#include <cuda_fp16.h>
#include <math.h>
#include <stdint.h>

// Problem constants
#define Bc   4
#define Lc   4096
#define Dc   1024
#define Hc   16
#define Dhc  64
#define Mtot (Bc*Lc)        // 16384 rows
#define NC   32             // scan chunks per sequence
#define CHUNK (Lc/NC)       // 128

// GEMM tiling: 128x128 tile, fp16 2-term (A hi only; W hi+lo), 2 CTAs/SM
#define MT 128
#define NT 128
#define KT 32               // k per stage
#define NKC (Dc/KT)         // 32 k-chunks
#define TILE_B (MT*KT*2)            // 8192 bytes per operand tile
#define OFF_AH 0
#define OFF_WH (TILE_B)
#define OFF_WL (2*TILE_B)
#define STAGE_BYTES (3*TILE_B)      // 24576
#define NSTAGE 4
#define GEMM_SMEM (NSTAGE*STAGE_BYTES)     // 98304 -> 2 CTAs/SM

// Conflict-free swizzle: 16B-chunk c (0..3) xored with (row>>1)&3.
#define SWZ(row, ch) ((uint32_t)(row) * 64 + (uint32_t)((((ch) ^ (((row) >> 1) & 3)) & 3) * 16))

// ---------------------------------------------------------------------------
// Scratch (__device__ globals per allocation-free rule)
// ---------------------------------------------------------------------------
__device__ __half g_qh[Mtot*Dc];               // q (fp16)
__device__ __half g_vh[Mtot*Dc];               // v (fp16)
__device__ __half g_gh[Mtot*Dc];               // gate pre-activation (fp16)
__device__ __half g_ret[Mtot*Dc];              // ret = q*s (fp16)
__device__ float g_chunkS[Bc*Hc*NC*Dhc];
__device__ float g_carry [Bc*Hc*NC*Dhc];
__device__ __half g_xh[Mtot*Dc];               // x in fp16
__device__ __half g_zh[Mtot*Dc];               // z in fp16
__device__ __half g_wh[4*Dc*Dc];               // Wq,Wv,Wg,Wo hi
__device__ __half g_wl[4*Dc*Dc];               // lo

// ---------------------------------------------------------------------------
// PTX helpers
// ---------------------------------------------------------------------------
__device__ __forceinline__ uint32_t smem_to_u32(const void* p) {
    uint32_t a;
    asm("{ .reg .u64 t; cvta.to.shared.u64 t, %1; cvt.u32.u64 %0, t; }" : "=r"(a) : "l"(p));
    return a;
}

#define CP16(dst, src) \
    asm volatile("cp.async.cg.shared.global [%0], [%1], 16;" :: "r"(dst), "l"(src) : "memory")

__device__ __forceinline__ void ldsm_x4(uint32_t (&r)[4], uint32_t addr) {
    asm volatile("ldmatrix.sync.aligned.m8n8.x4.shared.b16 {%0,%1,%2,%3}, [%4];"
        : "=r"(r[0]), "=r"(r[1]), "=r"(r[2]), "=r"(r[3]) : "r"(addr));
}

__device__ __forceinline__ void mma16816(float (&c)[4], const uint32_t (&a)[4],
                                         uint32_t b0, uint32_t b1) {
    asm volatile("mma.sync.aligned.m16n8k16.row.col.f32.f16.f16.f32 "
        "{%0,%1,%2,%3}, {%4,%5,%6,%7}, {%8,%9}, {%0,%1,%2,%3};"
        : "+f"(c[0]), "+f"(c[1]), "+f"(c[2]), "+f"(c[3])
        : "r"(a[0]), "r"(a[1]), "r"(a[2]), "r"(a[3]), "r"(b0), "r"(b1));
}

// ---------------------------------------------------------------------------
// Weight split fp32 -> (hi fp16, lo fp16); batched over 4 weights
// ---------------------------------------------------------------------------
struct SplitWArgs {
    const float* src[4];
    __half* hi[4];
    __half* lo[4];
};

__global__ __launch_bounds__(256)
void split_w_kernel(const SplitWArgs args)
{
    const int z = blockIdx.y;
    const float* s = args.src[z];
    __half* hi = args.hi[z];
    __half* lo = args.lo[z];

    int i = blockIdx.x * 256 + threadIdx.x;
    if (i >= Dc*Dc/4) return;
    float4 f = ((const float4*)s)[i];
    __half h0 = __float2half_rn(f.x), h1 = __float2half_rn(f.y);
    __half h2 = __float2half_rn(f.z), h3 = __float2half_rn(f.w);
    __half l0 = __float2half_rn(f.x - __half2float(h0));
    __half l1 = __float2half_rn(f.y - __half2float(h1));
    __half l2 = __float2half_rn(f.z - __half2float(h2));
    __half l3 = __float2half_rn(f.w - __half2float(h3));
    __half2 hp0(h0, h1), hp1(h2, h3), lp0(l0, l1), lp1(l2, l3);
    uint2 hv, lv;
    hv.x = *(uint32_t*)&hp0; hv.y = *(uint32_t*)&hp1;
    lv.x = *(uint32_t*)&lp0; lv.y = *(uint32_t*)&lp1;
    ((uint2*)hi)[i] = hv;
    ((uint2*)lo)[i] = lv;
}

// Activation convert fp32 -> fp16 (hi only)
__global__ __launch_bounds__(256)
void cvt_kernel(const float* __restrict__ s, __half* __restrict__ hi, int n4)
{
    int i = blockIdx.x * 256 + threadIdx.x;
    if (i >= n4) return;
    float4 f = ((const float4*)s)[i];
    __half2 hp0 = __floats2half2_rn(f.x, f.y);
    __half2 hp1 = __floats2half2_rn(f.z, f.w);
    uint2 hv;
    hv.x = *(uint32_t*)&hp0; hv.y = *(uint32_t*)&hp1;
    ((uint2*)hi)[i] = hv;
}

// ---------------------------------------------------------------------------
// mma.sync GEMM: C[m,n] = sum_k A[m,k]*W[n,k], fp16 2-term.
// 128x128 CTA tile, 8 warps (32x64 each), K-chunk 32, 4-stage, 2 CTAs/SM.
// OutT = __half (intermediates) or float (final output).
// ---------------------------------------------------------------------------
template <typename OutT>
struct GemmArgs {
    const __half* Ah;
    const __half* Wh[3];
    const __half* Wl[3];
    OutT* C[3];
};

template <typename OutT>
__global__ __launch_bounds__(256, 2)
void gemm_mma(const GemmArgs<OutT> args)
{
    extern __shared__ char smem[];
    const uint32_t sbase = smem_to_u32(smem);
    const int tid  = threadIdx.x;
    const int lane = tid & 31;
    const int wid  = tid >> 5;
    const int wm   = wid & 3;
    const int wn   = wid >> 2;
    const int bn   = blockIdx.x * NT;
    const int bm   = blockIdx.y * MT;
    const int z    = blockIdx.z;

    const __half* __restrict__ Ah = args.Ah;
    const __half* __restrict__ Wh = args.Wh[z];
    const __half* __restrict__ Wl = args.Wl[z];
    OutT* __restrict__ C = args.C[z];

    const int row0 = tid >> 2;
    const int ch0  = tid & 3;

    auto load_stage = [&](int st, int kc) {
        const uint32_t sb = sbase + (uint32_t)st * STAGE_BYTES;
        const int k0 = kc * KT;
        #pragma unroll
        for (int rep = 0; rep < 2; rep++) {
            int row = row0 + rep * 64;
            uint32_t sw = SWZ(row, ch0);
            const __half* pa = Ah + (size_t)(bm + row) * Dc + k0 + ch0 * 8;
            const __half* pw = Wh + (size_t)(bn + row) * Dc + k0 + ch0 * 8;
            const __half* pq = Wl + (size_t)(bn + row) * Dc + k0 + ch0 * 8;
            CP16(sb + OFF_AH + sw, pa);
            CP16(sb + OFF_WH + sw, pw);
            CP16(sb + OFF_WL + sw, pq);
        }
        asm volatile("cp.async.commit_group;" ::: "memory");
    };

    float c[2][8][4];
    #pragma unroll
    for (int i = 0; i < 2; i++)
        #pragma unroll
        for (int j = 0; j < 8; j++)
            #pragma unroll
            for (int k = 0; k < 4; k++) c[i][j][k] = 0.0f;

    load_stage(0, 0);
    load_stage(1, 1);
    load_stage(2, 2);

    const int a_r  = lane & 15;
    const int a_kc = lane >> 4;
    const int b_r  = ((lane >> 4) << 3) + (lane & 7);
    const int b_kc = (lane >> 3) & 1;

    for (int kc = 0; kc < NKC; kc++) {
        const int st = kc % NSTAGE;
        asm volatile("cp.async.wait_group 2;" ::: "memory");
        __syncthreads();

        if (kc + 3 < NKC) load_stage((kc + 3) % NSTAGE, kc + 3);
        else asm volatile("cp.async.commit_group;" ::: "memory");

        const uint32_t sb = sbase + (uint32_t)st * STAGE_BYTES;

        #pragma unroll
        for (int ks = 0; ks < 2; ks++) {
            uint32_t ah[2][4];
            #pragma unroll
            for (int mi = 0; mi < 2; mi++) {
                int row = wm * 32 + mi * 16 + a_r;
                int kk  = ks * 2 + a_kc;
                ldsm_x4(ah[mi], sb + OFF_AH + SWZ(row, kk));
            }
            #pragma unroll
            for (int half = 0; half < 2; half++) {
                uint32_t bh[2][4], bl[2][4];
                #pragma unroll
                for (int p = 0; p < 2; p++) {
                    int pr  = half * 2 + p;
                    int row = wn * 64 + pr * 16 + b_r;
                    int kk  = ks * 2 + b_kc;
                    uint32_t sw = SWZ(row, kk);
                    ldsm_x4(bh[p], sb + OFF_WH + sw);
                    ldsm_x4(bl[p], sb + OFF_WL + sw);
                }
                #pragma unroll
                for (int mi = 0; mi < 2; mi++)
                    #pragma unroll
                    for (int p = 0; p < 2; p++) {
                        int ni = (half * 2 + p) * 2;
                        mma16816(c[mi][ni+0], ah[mi], bh[p][0], bh[p][1]);
                        mma16816(c[mi][ni+1], ah[mi], bh[p][2], bh[p][3]);
                    }
                #pragma unroll
                for (int mi = 0; mi < 2; mi++)
                    #pragma unroll
                    for (int p = 0; p < 2; p++) {
                        int ni = (half * 2 + p) * 2;
                        mma16816(c[mi][ni+0], ah[mi], bl[p][0], bl[p][1]);
                        mma16816(c[mi][ni+1], ah[mi], bl[p][2], bl[p][3]);
                    }
            }
        }
    }

    const int er = lane >> 2;
    const int ec = (lane & 3) * 2;
    #pragma unroll
    for (int mi = 0; mi < 2; mi++) {
        #pragma unroll
        for (int ni = 0; ni < 8; ni++) {
            size_t r0g = (size_t)(bm + wm * 32 + mi * 16 + er);
            size_t cg  = (size_t)(bn + wn * 64 + ni * 8 + ec);
            if constexpr (sizeof(OutT) == 4) {
                float2* p0 = (float2*)((float*)C + r0g * Dc + cg);
                float2* p1 = (float2*)((float*)C + (r0g + 8) * Dc + cg);
                *p0 = make_float2(c[mi][ni][0], c[mi][ni][1]);
                *p1 = make_float2(c[mi][ni][2], c[mi][ni][3]);
            } else {
                __half2 h0 = __floats2half2_rn(c[mi][ni][0], c[mi][ni][1]);
                __half2 h1 = __floats2half2_rn(c[mi][ni][2], c[mi][ni][3]);
                *(__half2*)((__half*)C + r0g * Dc + cg)       = h0;
                *(__half2*)((__half*)C + (r0g + 8) * Dc + cg) = h1;
            }
        }
    }
}

// ---------------------------------------------------------------------------
// Retention scan (fp16 storage, fp32 accumulation)
// ---------------------------------------------------------------------------
__device__ __forceinline__ float lam_of(const float* beta, int h)
{
    float lam = 1.0f - exp2f(-beta[h]);
    lam = fmaxf(lam, 1.17549435e-38f);
    lam = fminf(lam, 1.0f);
    return lam;
}

// Pass 1: 16 outstanding loads per thread
__global__ __launch_bounds__(64)
void scan_pass1(const __half* __restrict__ v, const float* __restrict__ beta)
{
    int blk = blockIdx.x;
    int cc  = blk % NC;
    int bh  = blk / NC;
    int h   = bh % Hc;
    int b   = bh / Hc;
    int dh  = threadIdx.x;

    float lam = lam_of(beta, h);
    size_t off = ((size_t)(b*Lc + cc*CHUNK)) * Dc + h*Dhc + dh;

    float s = 0.0f;
    #pragma unroll
    for (int t0 = 0; t0 < CHUNK; t0 += 16) {
        __half vals[16];
        #pragma unroll
        for (int j = 0; j < 16; j++)
            vals[j] = v[off + (size_t)j * Dc];
        #pragma unroll
        for (int j = 0; j < 16; j++)
            s = fmaf(lam, s, __half2float(vals[j]));
        off += (size_t)16 * Dc;
    }
    g_chunkS[(size_t)(bh*NC + cc)*Dhc + dh] = s;
}

// Pass 2: batched loads, register scan.
__global__ __launch_bounds__(256)
void scan_pass2(const float* __restrict__ beta)
{
    int idx = blockIdx.x * blockDim.x + threadIdx.x;  // 0..4095
    int dh  = idx & 63;
    int bh  = idx >> 6;
    int h   = bh & (Hc - 1);

    float lam = lam_of(beta, h);
    float lamP = lam;
    #pragma unroll
    for (int i = 0; i < 7; i++) lamP = lamP * lamP;   // lam^128

    float cs[NC];
    #pragma unroll
    for (int cc = 0; cc < NC; cc++)
        cs[cc] = g_chunkS[(size_t)(bh*NC + cc)*Dhc + dh];

    float carry = 0.0f;
    #pragma unroll
    for (int cc = 0; cc < NC; cc++) {
        g_carry[(size_t)(bh*NC + cc)*Dhc + dh] = carry;
        carry = fmaf(lamP, carry, cs[cc]);
    }
}

// Pass 3: 8-deep batched loads, writes ret fp16.
__global__ __launch_bounds__(64)
void scan_pass3(const __half* __restrict__ v, const __half* __restrict__ q,
                __half* __restrict__ ret, const float* __restrict__ beta)
{
    int blk = blockIdx.x;
    int cc  = blk % NC;
    int bh  = blk / NC;
    int h   = bh % Hc;
    int b   = bh / Hc;
    int dh  = threadIdx.x;

    float lam = lam_of(beta, h);
    size_t off = ((size_t)(b*Lc + cc*CHUNK)) * Dc + h*Dhc + dh;

    float s = g_carry[(size_t)(bh*NC + cc)*Dhc + dh];
    #pragma unroll
    for (int t0 = 0; t0 < CHUNK; t0 += 8) {
        __half vv[8], qq[8];
        #pragma unroll
        for (int j = 0; j < 8; j++) {
            vv[j] = v[off + (size_t)j * Dc];
            qq[j] = q[off + (size_t)j * Dc];
        }
        #pragma unroll
        for (int j = 0; j < 8; j++) {
            s = fmaf(lam, s, __half2float(vv[j]));
            ret[off + (size_t)j * Dc] = __float2half_rn(__half2float(qq[j]) * s);
        }
        off += (size_t)8 * Dc;
    }
}

// ---------------------------------------------------------------------------
// Fused LayerNorm(ret) * SiLU(gate) -> z fp16 (fp16 in, fp32 reduce)
// ---------------------------------------------------------------------------
__global__ __launch_bounds__(256)
void ln_gate_kernel(const __half* __restrict__ ret, const __half* __restrict__ gate,
                    const float* __restrict__ gamma, const float* __restrict__ lbeta,
                    __half* __restrict__ zh)
{
    const size_t row = blockIdx.x;
    const int tid = threadIdx.x;

    uint2 rv = ((const uint2*)(ret  + row*Dc))[tid];
    uint2 gv = ((const uint2*)(gate + row*Dc))[tid];
    __half2 r01 = *(__half2*)&rv.x, r23 = *(__half2*)&rv.y;
    __half2 g01 = *(__half2*)&gv.x, g23 = *(__half2*)&gv.y;
    float r0 = __half2float(r01.x), r1 = __half2float(r01.y);
    float r2 = __half2float(r23.x), r3 = __half2float(r23.y);
    float g0 = __half2float(g01.x), g1 = __half2float(g01.y);
    float g2 = __half2float(g23.x), g3 = __half2float(g23.y);

    float s  = r0 + r1 + r2 + r3;
    float ss = r0*r0 + r1*r1 + r2*r2 + r3*r3;

    #pragma unroll
    for (int o = 16; o > 0; o >>= 1) {
        s  += __shfl_xor_sync(0xffffffffu, s,  o);
        ss += __shfl_xor_sync(0xffffffffu, ss, o);
    }
    __shared__ float shs[8], shq[8];
    if ((tid & 31) == 0) { shs[tid>>5] = s; shq[tid>>5] = ss; }
    __syncthreads();

    float tot = 0.0f, totq = 0.0f;
    #pragma unroll
    for (int i = 0; i < 8; i++) { tot += shs[i]; totq += shq[i]; }

    const float inv = 1.0f / (float)Dc;
    float mu   = tot * inv;
    float var  = totq * inv - mu * mu;
    float rstd = rsqrtf(var + 1e-5f);

    const float4 gm = ((const float4*)gamma)[tid];
    const float4 bt = ((const float4*)lbeta)[tid];

    float o0 = ((r0 - mu)*rstd*gm.x + bt.x) * (g0 / (1.0f + expf(-g0)));
    float o1 = ((r1 - mu)*rstd*gm.y + bt.y) * (g1 / (1.0f + expf(-g1)));
    float o2 = ((r2 - mu)*rstd*gm.z + bt.z) * (g2 / (1.0f + expf(-g2)));
    float o3 = ((r3 - mu)*rstd*gm.w + bt.w) * (g3 / (1.0f + expf(-g3)));

    __half2 hp0 = __floats2half2_rn(o0, o1);
    __half2 hp1 = __floats2half2_rn(o2, o3);
    uint2 hv;
    hv.x = *(uint32_t*)&hp0; hv.y = *(uint32_t*)&hp1;
    ((uint2*)(zh + row*Dc))[tid] = hv;
}

// ---------------------------------------------------------------------------
// Launch
// ---------------------------------------------------------------------------
extern "C" void kernel_launch(void* const* d_in, const int* in_sizes, int n_in,
                              void* d_out, int out_size)
{
    const float* x      = (const float*)d_in[0];
    const float* Wq     = (const float*)d_in[1];
    const float* Wv     = (const float*)d_in[2];
    const float* Wo     = (const float*)d_in[3];
    const float* Wg     = (const float*)d_in[4];
    const float* beta   = (const float*)d_in[5];
    const float* gamma  = (const float*)d_in[6];
    const float* lbeta  = (const float*)d_in[7];
    float* out          = (float*)d_out;

    __half *qh, *vh, *gh, *ret, *xh, *zh, *wh, *wl;
    cudaGetSymbolAddress((void**)&qh, g_qh);
    cudaGetSymbolAddress((void**)&vh, g_vh);
    cudaGetSymbolAddress((void**)&gh, g_gh);
    cudaGetSymbolAddress((void**)&ret, g_ret);
    cudaGetSymbolAddress((void**)&xh, g_xh);
    cudaGetSymbolAddress((void**)&zh, g_zh);
    cudaGetSymbolAddress((void**)&wh, g_wh);
    cudaGetSymbolAddress((void**)&wl, g_wl);

    cudaFuncSetAttribute(gemm_mma<__half>, cudaFuncAttributeMaxDynamicSharedMemorySize, GEMM_SMEM);
    cudaFuncSetAttribute(gemm_mma<float>,  cudaFuncAttributeMaxDynamicSharedMemorySize, GEMM_SMEM);

    // Weight splits (4 weights, batched)
    SplitWArgs sw;
    sw.src[0] = Wq; sw.hi[0] = wh + 0*(size_t)Dc*Dc; sw.lo[0] = wl + 0*(size_t)Dc*Dc;
    sw.src[1] = Wv; sw.hi[1] = wh + 1*(size_t)Dc*Dc; sw.lo[1] = wl + 1*(size_t)Dc*Dc;
    sw.src[2] = Wg; sw.hi[2] = wh + 2*(size_t)Dc*Dc; sw.lo[2] = wl + 2*(size_t)Dc*Dc;
    sw.src[3] = Wo; sw.hi[3] = wh + 3*(size_t)Dc*Dc; sw.lo[3] = wl + 3*(size_t)Dc*Dc;
    dim3 wgrid((Dc*Dc/4 + 255)/256, 4);
    split_w_kernel<<<wgrid, 256>>>(sw);

    // x -> fp16
    cvt_kernel<<<(Mtot*Dc/4 + 255)/256, 256>>>(x, xh, Mtot*Dc/4);

    // Fused q/v/g projection GEMMs (fp16 outputs)
    GemmArgs<__half> a1;
    a1.Ah = xh;
    a1.Wh[0] = wh + 0*(size_t)Dc*Dc; a1.Wl[0] = wl + 0*(size_t)Dc*Dc; a1.C[0] = qh;
    a1.Wh[1] = wh + 1*(size_t)Dc*Dc; a1.Wl[1] = wl + 1*(size_t)Dc*Dc; a1.C[1] = vh;
    a1.Wh[2] = wh + 2*(size_t)Dc*Dc; a1.Wl[2] = wl + 2*(size_t)Dc*Dc; a1.C[2] = gh;
    dim3 grid_qvg(Dc/NT, Mtot/MT, 3);   // (8, 128, 3)
    gemm_mma<__half><<<grid_qvg, 256, GEMM_SMEM>>>(a1);

    scan_pass1<<<Bc*Hc*NC, 64>>>(vh, beta);
    scan_pass2<<<(Bc*Hc*Dhc)/256, 256>>>(beta);
    scan_pass3<<<Bc*Hc*NC, 64>>>(vh, qh, ret, beta);

    ln_gate_kernel<<<Mtot, 256>>>(ret, gh, gamma, lbeta, zh);

    // Output GEMM (fp32 output)
    GemmArgs<float> a2;
    a2.Ah = zh;
    a2.Wh[0] = wh + 3*(size_t)Dc*Dc; a2.Wl[0] = wl + 3*(size_t)Dc*Dc; a2.C[0] = out;
    a2.Wh[1] = a2.Wh[0]; a2.Wl[1] = a2.Wl[0]; a2.C[1] = out;
    a2.Wh[2] = a2.Wh[0]; a2.Wl[2] = a2.Wl[0]; a2.C[2] = out;
    dim3 grid_o(Dc/NT, Mtot/MT, 1);     // (8, 128, 1)
    gemm_mma<float><<<grid_o, 256, GEMM_SMEM>>>(a2);
}

// round 12
// speedup vs baseline: 2.0640x; 1.4009x over previous
#include <cuda_runtime.h>
#include <cuda_fp16.h>
#include <math.h>
#include <stdint.h>

// Problem constants
#define Bc   4
#define Lc   4096
#define Dc   1024
#define Hc   16
#define Dhc  64
#define Mtot (Bc*Lc)        // 16384 rows
#define NC   32             // scan chunks per sequence
#define CHUNK (Lc/NC)       // 128

// GEMM tiling: 128x128 tile, 2 CTAs/SM
#define MT 128
#define NT 128
#define KT 32               // k per stage
#define NKC (Dc/KT)         // 32 k-chunks
#define TILE_B (MT*KT*2)            // 8192 bytes per operand tile
#define OFF_AH 0
#define OFF_WH (TILE_B)
#define OFF_WL (2*TILE_B)
#define STAGE_BYTES (3*TILE_B)      // 24576
#define NSTAGE 4
#define GEMM_SMEM (NSTAGE*STAGE_BYTES)     // 98304 -> 2 CTAs/SM

// Conflict-free swizzle: 16B-chunk c (0..3) xored with (row>>1)&3.
#define SWZ(row, ch) ((uint32_t)(row) * 64 + (uint32_t)((((ch) ^ (((row) >> 1) & 3)) & 3) * 16))

// ---------------------------------------------------------------------------
// Scratch (__device__ globals per allocation-free rule)
// ---------------------------------------------------------------------------
__device__ __half g_qh[Mtot*Dc];               // q (fp16)
__device__ __half g_vh[Mtot*Dc];               // v (fp16)
__device__ __half g_gh[Mtot*Dc];               // gate pre-activation (fp16)
__device__ __half g_ret[Mtot*Dc];              // ret = q*s (fp16)
__device__ float g_chunkS[Bc*Hc*NC*Dhc];
__device__ float g_carry [Bc*Hc*NC*Dhc];
__device__ __half g_xh[Mtot*Dc];               // x in fp16
__device__ __half g_zh[Mtot*Dc];               // z in fp16
__device__ __half g_wh[4*Dc*Dc];               // Wq,Wv,Wg,Wo hi
__device__ __half g_wl[4*Dc*Dc];               // lo (used by output GEMM only)

// ---------------------------------------------------------------------------
// PTX helpers
// ---------------------------------------------------------------------------
__device__ __forceinline__ uint32_t smem_to_u32(const void* p) {
    uint32_t a;
    asm("{ .reg .u64 t; cvta.to.shared.u64 t, %1; cvt.u32.u64 %0, t; }" : "=r"(a) : "l"(p));
    return a;
}

#define CP16(dst, src) \
    asm volatile("cp.async.cg.shared.global [%0], [%1], 16;" :: "r"(dst), "l"(src) : "memory")

__device__ __forceinline__ void ldsm_x4(uint32_t (&r)[4], uint32_t addr) {
    asm volatile("ldmatrix.sync.aligned.m8n8.x4.shared.b16 {%0,%1,%2,%3}, [%4];"
        : "=r"(r[0]), "=r"(r[1]), "=r"(r[2]), "=r"(r[3]) : "r"(addr));
}

__device__ __forceinline__ void mma16816(float (&c)[4], const uint32_t (&a)[4],
                                         uint32_t b0, uint32_t b1) {
    asm volatile("mma.sync.aligned.m16n8k16.row.col.f32.f16.f16.f32 "
        "{%0,%1,%2,%3}, {%4,%5,%6,%7}, {%8,%9}, {%0,%1,%2,%3};"
        : "+f"(c[0]), "+f"(c[1]), "+f"(c[2]), "+f"(c[3])
        : "r"(a[0]), "r"(a[1]), "r"(a[2]), "r"(a[3]), "r"(b0), "r"(b1));
}

// ---------------------------------------------------------------------------
// Weight split fp32 -> (hi fp16, lo fp16); batched over 4 weights
// ---------------------------------------------------------------------------
struct SplitWArgs {
    const float* src[4];
    __half* hi[4];
    __half* lo[4];
};

__global__ __launch_bounds__(256)
void split_w_kernel(const SplitWArgs args)
{
    const int z = blockIdx.y;
    const float* s = args.src[z];
    __half* hi = args.hi[z];
    __half* lo = args.lo[z];

    int i = blockIdx.x * 256 + threadIdx.x;
    if (i >= Dc*Dc/4) return;
    float4 f = ((const float4*)s)[i];
    __half h0 = __float2half_rn(f.x), h1 = __float2half_rn(f.y);
    __half h2 = __float2half_rn(f.z), h3 = __float2half_rn(f.w);
    __half l0 = __float2half_rn(f.x - __half2float(h0));
    __half l1 = __float2half_rn(f.y - __half2float(h1));
    __half l2 = __float2half_rn(f.z - __half2float(h2));
    __half l3 = __float2half_rn(f.w - __half2float(h3));
    __half2 hp0(h0, h1), hp1(h2, h3), lp0(l0, l1), lp1(l2, l3);
    uint2 hv, lv;
    hv.x = *(uint32_t*)&hp0; hv.y = *(uint32_t*)&hp1;
    lv.x = *(uint32_t*)&lp0; lv.y = *(uint32_t*)&lp1;
    ((uint2*)hi)[i] = hv;
    ((uint2*)lo)[i] = lv;
}

// Activation convert fp32 -> fp16 (hi only)
__global__ __launch_bounds__(256)
void cvt_kernel(const float* __restrict__ s, __half* __restrict__ hi, int n4)
{
    int i = blockIdx.x * 256 + threadIdx.x;
    if (i >= n4) return;
    float4 f = ((const float4*)s)[i];
    __half2 hp0 = __floats2half2_rn(f.x, f.y);
    __half2 hp1 = __floats2half2_rn(f.z, f.w);
    uint2 hv;
    hv.x = *(uint32_t*)&hp0; hv.y = *(uint32_t*)&hp1;
    ((uint2*)hi)[i] = hv;
}

// ---------------------------------------------------------------------------
// mma.sync GEMM: C[m,n] = sum_k A[m,k]*W[n,k].
// TERMS=1: pure fp16 (A x Wh). TERMS=2: fp16 2-term (A x Wh + A x Wl).
// 128x128 CTA tile, 8 warps (32x64 each), K-chunk 32, 4-stage, 2 CTAs/SM.
// ---------------------------------------------------------------------------
template <typename OutT>
struct GemmArgs {
    const __half* Ah;
    const __half* Wh[3];
    const __half* Wl[3];
    OutT* C[3];
};

template <typename OutT, int TERMS>
__global__ __launch_bounds__(256, 2)
void gemm_mma(const GemmArgs<OutT> args)
{
    extern __shared__ char smem[];
    const uint32_t sbase = smem_to_u32(smem);
    const int tid  = threadIdx.x;
    const int lane = tid & 31;
    const int wid  = tid >> 5;
    const int wm   = wid & 3;
    const int wn   = wid >> 2;
    const int bn   = blockIdx.x * NT;
    const int bm   = blockIdx.y * MT;
    const int z    = blockIdx.z;

    const __half* __restrict__ Ah = args.Ah;
    const __half* __restrict__ Wh = args.Wh[z];
    const __half* __restrict__ Wl = args.Wl[z];
    OutT* __restrict__ C = args.C[z];

    const int row0 = tid >> 2;
    const int ch0  = tid & 3;

    auto load_stage = [&](int st, int kc) {
        const uint32_t sb = sbase + (uint32_t)st * STAGE_BYTES;
        const int k0 = kc * KT;
        #pragma unroll
        for (int rep = 0; rep < 2; rep++) {
            int row = row0 + rep * 64;
            uint32_t sw = SWZ(row, ch0);
            const __half* pa = Ah + (size_t)(bm + row) * Dc + k0 + ch0 * 8;
            const __half* pw = Wh + (size_t)(bn + row) * Dc + k0 + ch0 * 8;
            CP16(sb + OFF_AH + sw, pa);
            CP16(sb + OFF_WH + sw, pw);
            if (TERMS == 2) {
                const __half* pq = Wl + (size_t)(bn + row) * Dc + k0 + ch0 * 8;
                CP16(sb + OFF_WL + sw, pq);
            }
        }
        asm volatile("cp.async.commit_group;" ::: "memory");
    };

    float c[2][8][4];
    #pragma unroll
    for (int i = 0; i < 2; i++)
        #pragma unroll
        for (int j = 0; j < 8; j++)
            #pragma unroll
            for (int k = 0; k < 4; k++) c[i][j][k] = 0.0f;

    load_stage(0, 0);
    load_stage(1, 1);
    load_stage(2, 2);

    const int a_r  = lane & 15;
    const int a_kc = lane >> 4;
    const int b_r  = ((lane >> 4) << 3) + (lane & 7);
    const int b_kc = (lane >> 3) & 1;

    for (int kc = 0; kc < NKC; kc++) {
        const int st = kc % NSTAGE;
        asm volatile("cp.async.wait_group 2;" ::: "memory");
        __syncthreads();

        if (kc + 3 < NKC) load_stage((kc + 3) % NSTAGE, kc + 3);
        else asm volatile("cp.async.commit_group;" ::: "memory");

        const uint32_t sb = sbase + (uint32_t)st * STAGE_BYTES;

        #pragma unroll
        for (int ks = 0; ks < 2; ks++) {
            uint32_t ah[2][4];
            #pragma unroll
            for (int mi = 0; mi < 2; mi++) {
                int row = wm * 32 + mi * 16 + a_r;
                int kk  = ks * 2 + a_kc;
                ldsm_x4(ah[mi], sb + OFF_AH + SWZ(row, kk));
            }
            #pragma unroll
            for (int half = 0; half < 2; half++) {
                uint32_t bh[2][4], bl[2][4];
                #pragma unroll
                for (int p = 0; p < 2; p++) {
                    int pr  = half * 2 + p;
                    int row = wn * 64 + pr * 16 + b_r;
                    int kk  = ks * 2 + b_kc;
                    uint32_t sw = SWZ(row, kk);
                    ldsm_x4(bh[p], sb + OFF_WH + sw);
                    if (TERMS == 2) ldsm_x4(bl[p], sb + OFF_WL + sw);
                }
                #pragma unroll
                for (int mi = 0; mi < 2; mi++)
                    #pragma unroll
                    for (int p = 0; p < 2; p++) {
                        int ni = (half * 2 + p) * 2;
                        mma16816(c[mi][ni+0], ah[mi], bh[p][0], bh[p][1]);
                        mma16816(c[mi][ni+1], ah[mi], bh[p][2], bh[p][3]);
                    }
                if (TERMS == 2) {
                    #pragma unroll
                    for (int mi = 0; mi < 2; mi++)
                        #pragma unroll
                        for (int p = 0; p < 2; p++) {
                            int ni = (half * 2 + p) * 2;
                            mma16816(c[mi][ni+0], ah[mi], bl[p][0], bl[p][1]);
                            mma16816(c[mi][ni+1], ah[mi], bl[p][2], bl[p][3]);
                        }
                }
            }
        }
    }

    const int er = lane >> 2;
    const int ec = (lane & 3) * 2;
    #pragma unroll
    for (int mi = 0; mi < 2; mi++) {
        #pragma unroll
        for (int ni = 0; ni < 8; ni++) {
            size_t r0g = (size_t)(bm + wm * 32 + mi * 16 + er);
            size_t cg  = (size_t)(bn + wn * 64 + ni * 8 + ec);
            if constexpr (sizeof(OutT) == 4) {
                float2* p0 = (float2*)((float*)C + r0g * Dc + cg);
                float2* p1 = (float2*)((float*)C + (r0g + 8) * Dc + cg);
                *p0 = make_float2(c[mi][ni][0], c[mi][ni][1]);
                *p1 = make_float2(c[mi][ni][2], c[mi][ni][3]);
            } else {
                __half2 h0 = __floats2half2_rn(c[mi][ni][0], c[mi][ni][1]);
                __half2 h1 = __floats2half2_rn(c[mi][ni][2], c[mi][ni][3]);
                *(__half2*)((__half*)C + r0g * Dc + cg)       = h0;
                *(__half2*)((__half*)C + (r0g + 8) * Dc + cg) = h1;
            }
        }
    }
}

// ---------------------------------------------------------------------------
// Retention scan (fp16 storage, fp32 accumulation)
// ---------------------------------------------------------------------------
__device__ __forceinline__ float lam_of(const float* beta, int h)
{
    float lam = 1.0f - exp2f(-beta[h]);
    lam = fmaxf(lam, 1.17549435e-38f);
    lam = fminf(lam, 1.0f);
    return lam;
}

__global__ __launch_bounds__(64)
void scan_pass1(const __half* __restrict__ v, const float* __restrict__ beta)
{
    int blk = blockIdx.x;
    int cc  = blk % NC;
    int bh  = blk / NC;
    int h   = bh % Hc;
    int b   = bh / Hc;
    int dh  = threadIdx.x;

    float lam = lam_of(beta, h);
    size_t off = ((size_t)(b*Lc + cc*CHUNK)) * Dc + h*Dhc + dh;

    float s = 0.0f;
    #pragma unroll
    for (int t0 = 0; t0 < CHUNK; t0 += 16) {
        __half vals[16];
        #pragma unroll
        for (int j = 0; j < 16; j++)
            vals[j] = v[off + (size_t)j * Dc];
        #pragma unroll
        for (int j = 0; j < 16; j++)
            s = fmaf(lam, s, __half2float(vals[j]));
        off += (size_t)16 * Dc;
    }
    g_chunkS[(size_t)(bh*NC + cc)*Dhc + dh] = s;
}

__global__ __launch_bounds__(256)
void scan_pass2(const float* __restrict__ beta)
{
    int idx = blockIdx.x * blockDim.x + threadIdx.x;  // 0..4095
    int dh  = idx & 63;
    int bh  = idx >> 6;
    int h   = bh & (Hc - 1);

    float lam = lam_of(beta, h);
    float lamP = lam;
    #pragma unroll
    for (int i = 0; i < 7; i++) lamP = lamP * lamP;   // lam^128

    float cs[NC];
    #pragma unroll
    for (int cc = 0; cc < NC; cc++)
        cs[cc] = g_chunkS[(size_t)(bh*NC + cc)*Dhc + dh];

    float carry = 0.0f;
    #pragma unroll
    for (int cc = 0; cc < NC; cc++) {
        g_carry[(size_t)(bh*NC + cc)*Dhc + dh] = carry;
        carry = fmaf(lamP, carry, cs[cc]);
    }
}

__global__ __launch_bounds__(64)
void scan_pass3(const __half* __restrict__ v, const __half* __restrict__ q,
                __half* __restrict__ ret, const float* __restrict__ beta)
{
    int blk = blockIdx.x;
    int cc  = blk % NC;
    int bh  = blk / NC;
    int h   = bh % Hc;
    int b   = bh / Hc;
    int dh  = threadIdx.x;

    float lam = lam_of(beta, h);
    size_t off = ((size_t)(b*Lc + cc*CHUNK)) * Dc + h*Dhc + dh;

    float s = g_carry[(size_t)(bh*NC + cc)*Dhc + dh];
    #pragma unroll
    for (int t0 = 0; t0 < CHUNK; t0 += 8) {
        __half vv[8], qq[8];
        #pragma unroll
        for (int j = 0; j < 8; j++) {
            vv[j] = v[off + (size_t)j * Dc];
            qq[j] = q[off + (size_t)j * Dc];
        }
        #pragma unroll
        for (int j = 0; j < 8; j++) {
            s = fmaf(lam, s, __half2float(vv[j]));
            ret[off + (size_t)j * Dc] = __float2half_rn(__half2float(qq[j]) * s);
        }
        off += (size_t)8 * Dc;
    }
}

// ---------------------------------------------------------------------------
// Fused LayerNorm(ret) * SiLU(gate) -> z fp16 (fp16 in, fp32 reduce)
// ---------------------------------------------------------------------------
__global__ __launch_bounds__(256)
void ln_gate_kernel(const __half* __restrict__ ret, const __half* __restrict__ gate,
                    const float* __restrict__ gamma, const float* __restrict__ lbeta,
                    __half* __restrict__ zh)
{
    const size_t row = blockIdx.x;
    const int tid = threadIdx.x;

    uint2 rv = ((const uint2*)(ret  + row*Dc))[tid];
    uint2 gv = ((const uint2*)(gate + row*Dc))[tid];
    __half2 r01 = *(__half2*)&rv.x, r23 = *(__half2*)&rv.y;
    __half2 g01 = *(__half2*)&gv.x, g23 = *(__half2*)&gv.y;
    float r0 = __half2float(r01.x), r1 = __half2float(r01.y);
    float r2 = __half2float(r23.x), r3 = __half2float(r23.y);
    float g0 = __half2float(g01.x), g1 = __half2float(g01.y);
    float g2 = __half2float(g23.x), g3 = __half2float(g23.y);

    float s  = r0 + r1 + r2 + r3;
    float ss = r0*r0 + r1*r1 + r2*r2 + r3*r3;

    #pragma unroll
    for (int o = 16; o > 0; o >>= 1) {
        s  += __shfl_xor_sync(0xffffffffu, s,  o);
        ss += __shfl_xor_sync(0xffffffffu, ss, o);
    }
    __shared__ float shs[8], shq[8];
    if ((tid & 31) == 0) { shs[tid>>5] = s; shq[tid>>5] = ss; }
    __syncthreads();

    float tot = 0.0f, totq = 0.0f;
    #pragma unroll
    for (int i = 0; i < 8; i++) { tot += shs[i]; totq += shq[i]; }

    const float inv = 1.0f / (float)Dc;
    float mu   = tot * inv;
    float var  = totq * inv - mu * mu;
    float rstd = rsqrtf(var + 1e-5f);

    const float4 gm = ((const float4*)gamma)[tid];
    const float4 bt = ((const float4*)lbeta)[tid];

    float o0 = ((r0 - mu)*rstd*gm.x + bt.x) * (g0 / (1.0f + expf(-g0)));
    float o1 = ((r1 - mu)*rstd*gm.y + bt.y) * (g1 / (1.0f + expf(-g1)));
    float o2 = ((r2 - mu)*rstd*gm.z + bt.z) * (g2 / (1.0f + expf(-g2)));
    float o3 = ((r3 - mu)*rstd*gm.w + bt.w) * (g3 / (1.0f + expf(-g3)));

    __half2 hp0 = __floats2half2_rn(o0, o1);
    __half2 hp1 = __floats2half2_rn(o2, o3);
    uint2 hv;
    hv.x = *(uint32_t*)&hp0; hv.y = *(uint32_t*)&hp1;
    ((uint2*)(zh + row*Dc))[tid] = hv;
}

// ---------------------------------------------------------------------------
// Launch
// ---------------------------------------------------------------------------
extern "C" void kernel_launch(void* const* d_in, const int* in_sizes, int n_in,
                              void* d_out, int out_size)
{
    const float* x      = (const float*)d_in[0];
    const float* Wq     = (const float*)d_in[1];
    const float* Wv     = (const float*)d_in[2];
    const float* Wo     = (const float*)d_in[3];
    const float* Wg     = (const float*)d_in[4];
    const float* beta   = (const float*)d_in[5];
    const float* gamma  = (const float*)d_in[6];
    const float* lbeta  = (const float*)d_in[7];
    float* out          = (float*)d_out;

    __half *qh, *vh, *gh, *ret, *xh, *zh, *wh, *wl;
    cudaGetSymbolAddress((void**)&qh, g_qh);
    cudaGetSymbolAddress((void**)&vh, g_vh);
    cudaGetSymbolAddress((void**)&gh, g_gh);
    cudaGetSymbolAddress((void**)&ret, g_ret);
    cudaGetSymbolAddress((void**)&xh, g_xh);
    cudaGetSymbolAddress((void**)&zh, g_zh);
    cudaGetSymbolAddress((void**)&wh, g_wh);
    cudaGetSymbolAddress((void**)&wl, g_wl);

    cudaFuncSetAttribute((const void*)gemm_mma<__half,1>, cudaFuncAttributeMaxDynamicSharedMemorySize, GEMM_SMEM);
    cudaFuncSetAttribute((const void*)gemm_mma<float,2>,  cudaFuncAttributeMaxDynamicSharedMemorySize, GEMM_SMEM);

    // Weight splits (4 weights, batched)
    SplitWArgs sw;
    sw.src[0] = Wq; sw.hi[0] = wh + 0*(size_t)Dc*Dc; sw.lo[0] = wl + 0*(size_t)Dc*Dc;
    sw.src[1] = Wv; sw.hi[1] = wh + 1*(size_t)Dc*Dc; sw.lo[1] = wl + 1*(size_t)Dc*Dc;
    sw.src[2] = Wg; sw.hi[2] = wh + 2*(size_t)Dc*Dc; sw.lo[2] = wl + 2*(size_t)Dc*Dc;
    sw.src[3] = Wo; sw.hi[3] = wh + 3*(size_t)Dc*Dc; sw.lo[3] = wl + 3*(size_t)Dc*Dc;
    dim3 wgrid((Dc*Dc/4 + 255)/256, 4);
    split_w_kernel<<<wgrid, 256>>>(sw);

    // x -> fp16
    cvt_kernel<<<(Mtot*Dc/4 + 255)/256, 256>>>(x, xh, Mtot*Dc/4);

    // Fused q/v/g projection GEMMs (1-term fp16, fp16 outputs)
    GemmArgs<__half> a1;
    a1.Ah = xh;
    a1.Wh[0] = wh + 0*(size_t)Dc*Dc; a1.Wl[0] = wl + 0*(size_t)Dc*Dc; a1.C[0] = qh;
    a1.Wh[1] = wh + 1*(size_t)Dc*Dc; a1.Wl[1] = wl + 1*(size_t)Dc*Dc; a1.C[1] = vh;
    a1.Wh[2] = wh + 2*(size_t)Dc*Dc; a1.Wl[2] = wl + 2*(size_t)Dc*Dc; a1.C[2] = gh;
    dim3 grid_qvg(Dc/NT, Mtot/MT, 3);   // (8, 128, 3)
    gemm_mma<__half,1><<<grid_qvg, 256, GEMM_SMEM>>>(a1);

    scan_pass1<<<Bc*Hc*NC, 64>>>(vh, beta);
    scan_pass2<<<(Bc*Hc*Dhc)/256, 256>>>(beta);
    scan_pass3<<<Bc*Hc*NC, 64>>>(vh, qh, ret, beta);

    ln_gate_kernel<<<Mtot, 256>>>(ret, gh, gamma, lbeta, zh);

    // Output GEMM (2-term, fp32 output)
    GemmArgs<float> a2;
    a2.Ah = zh;
    a2.Wh[0] = wh + 3*(size_t)Dc*Dc; a2.Wl[0] = wl + 3*(size_t)Dc*Dc; a2.C[0] = out;
    a2.Wh[1] = a2.Wh[0]; a2.Wl[1] = a2.Wl[0]; a2.C[1] = out;
    a2.Wh[2] = a2.Wh[0]; a2.Wl[2] = a2.Wl[0]; a2.C[2] = out;
    dim3 grid_o(Dc/NT, Mtot/MT, 1);     // (8, 128, 1)
    gemm_mma<float,2><<<grid_o, 256, GEMM_SMEM>>>(a2);
}